// round 14
// baseline (speedup 1.0000x reference)
#include <cuda_runtime.h>
#include <cuda_bf16.h>
#include <stdint.h>
#include <math.h>

#define TOK   4096      // B*P
#define DMODEL 768
#define TD    2304      // 3*D
#define NHEAD 12
#define HD    64
#define SEQ   2048
#define NBATCH 2

// ---------------- scratch (no allocations allowed) ----------------
__device__ float  g_qkv[TOK * TD];      // [token, 3*D]
__device__ float  g_attn[TOK * DMODEL]; // attention output, pre-LN
__device__ float2 g_stat[TOK];          // (mean, rstd) of attention output rows

__device__ __forceinline__ void mma_bf16(float c[4], const uint32_t a[4], const uint32_t b[2])
{
    asm volatile(
        "mma.sync.aligned.m16n8k16.row.col.f32.bf16.bf16.f32 "
        "{%0,%1,%2,%3}, {%4,%5,%6,%7}, {%8,%9}, {%0,%1,%2,%3};"
        : "+f"(c[0]), "+f"(c[1]), "+f"(c[2]), "+f"(c[3])
        : "r"(a[0]), "r"(a[1]), "r"(a[2]), "r"(a[3]), "r"(b[0]), "r"(b[1]));
}

__device__ __forceinline__ void split_pack(float x0, float x1, uint32_t& hi, uint32_t& lo)
{
    __nv_bfloat16 h0 = __float2bfloat16(x0);
    __nv_bfloat16 h1 = __float2bfloat16(x1);
    __nv_bfloat16 l0 = __float2bfloat16(x0 - __bfloat162float(h0));
    __nv_bfloat16 l1 = __float2bfloat16(x1 - __bfloat162float(h1));
    hi = ((uint32_t)__bfloat16_as_ushort(h1) << 16) | (uint32_t)__bfloat16_as_ushort(h0);
    lo = ((uint32_t)__bfloat16_as_ushort(l1) << 16) | (uint32_t)__bfloat16_as_ushort(l0);
}

// =========================================================================
// bf16x3 tensor-core GEMM, 64x64 block / 128 threads / 4 blocks per SM.
// Same 32x32 warp tile and sandwich schedule as the proven kernel; the
// change is occupancy geometry: 4 independent barrier groups per SM.
//  MODE 1: QKV proj + fused per-head QK LayerNorm (+0.125 q). v plain.
//  MODE 2: out proj, A-load applies LN via precomputed stats, + bias.
// =========================================================================
#define SA 12
#define SB 24

template<int MODE>
__global__ void __launch_bounds__(128, 4) gemm_fused_kernel(
    const float* __restrict__ A, const float* __restrict__ B,
    const float* __restrict__ bias, float* __restrict__ C,
    int M, int N, int K,
    const float* __restrict__ qs, const float* __restrict__ qb,
    const float* __restrict__ ks, const float* __restrict__ kb,
    const float2* __restrict__ lnstat,
    const float* __restrict__ os, const float* __restrict__ ob)
{
    __shared__ uint32_t Ah[2][64][SA];
    __shared__ uint32_t Al[2][64][SA];
    __shared__ __nv_bfloat16 Bh[2][64][SB];
    __shared__ __nv_bfloat16 Bl[2][64][SB];
    __shared__ float2 red[64][2];

    const int tid  = threadIdx.x;
    const int lane = tid & 31;
    const int wid  = tid >> 5;          // 0..3
    const int wm   = wid & 1;
    const int wn   = wid >> 1;
    const int m0   = wm * 32;
    const int n0   = wn * 32;
    const int lr   = lane >> 2;
    const int lc   = lane & 3;

    const int blockM = blockIdx.y * 64;
    const int blockN = blockIdx.x * 64;

    // A: 64 rows x 16 k = 256 float4; thread covers rows am0, am0+32
    const int am0 = tid >> 2;             // 0..31
    const int ak4 = (tid & 3) * 4;        // 0,4,8,12
    const float* Aptr0 = A + (size_t)(blockM + am0) * K + ak4;
    const float* Aptr1 = A + (size_t)(blockM + am0 + 32) * K + ak4;
    // B: 16 k rows x 64 n = 256 float4; thread covers rows bk, bk+8
    const int bk  = tid >> 4;             // 0..7
    const int bn4 = (tid & 15) * 4;       // 0..60
    const float* Bptr0 = B + (size_t)bk * N + blockN + bn4;
    const float* Bptr1 = B + (size_t)(bk + 8) * N + blockN + bn4;

    float2 st0 = make_float2(0.f, 1.f), st1 = st0;
    if (MODE == 2) {
        st0 = lnstat[blockM + am0];
        st1 = lnstat[blockM + am0 + 32];
    }

    float acc[2][4][4];
#pragma unroll
    for (int i = 0; i < 2; i++)
#pragma unroll
        for (int j = 0; j < 4; j++)
#pragma unroll
            for (int k = 0; k < 4; k++) acc[i][j][k] = 0.f;

    const int T = K / 16;

    float4 aReg0 = *(const float4*)Aptr0;
    float4 aReg1 = *(const float4*)Aptr1;
    float4 bReg0 = *(const float4*)Bptr0;
    float4 bReg1 = *(const float4*)Bptr1;
    float4 osv = make_float4(1,1,1,1), obv = make_float4(0,0,0,0);
    if (MODE == 2) {
        osv = *(const float4*)(os + ak4);
        obv = *(const float4*)(ob + ak4);
    }

    auto storeTile = [&](int buf) {
        float4 a0 = aReg0, a1 = aReg1;
        if (MODE == 2) {
            a0.x = (a0.x - st0.x) * st0.y * osv.x + obv.x;
            a0.y = (a0.y - st0.x) * st0.y * osv.y + obv.y;
            a0.z = (a0.z - st0.x) * st0.y * osv.z + obv.z;
            a0.w = (a0.w - st0.x) * st0.y * osv.w + obv.w;
            a1.x = (a1.x - st1.x) * st1.y * osv.x + obv.x;
            a1.y = (a1.y - st1.x) * st1.y * osv.y + obv.y;
            a1.z = (a1.z - st1.x) * st1.y * osv.z + obv.z;
            a1.w = (a1.w - st1.x) * st1.y * osv.w + obv.w;
        }
        uint32_t h, l;
        split_pack(a0.x, a0.y, h, l);
        Ah[buf][am0][ak4 / 2] = h; Al[buf][am0][ak4 / 2] = l;
        split_pack(a0.z, a0.w, h, l);
        Ah[buf][am0][ak4 / 2 + 1] = h; Al[buf][am0][ak4 / 2 + 1] = l;
        split_pack(a1.x, a1.y, h, l);
        Ah[buf][am0 + 32][ak4 / 2] = h; Al[buf][am0 + 32][ak4 / 2] = l;
        split_pack(a1.z, a1.w, h, l);
        Ah[buf][am0 + 32][ak4 / 2 + 1] = h; Al[buf][am0 + 32][ak4 / 2 + 1] = l;

        const float bv0[4] = { bReg0.x, bReg0.y, bReg0.z, bReg0.w };
        const float bv1[4] = { bReg1.x, bReg1.y, bReg1.z, bReg1.w };
#pragma unroll
        for (int j = 0; j < 4; j++) {
            __nv_bfloat16 bh = __float2bfloat16(bv0[j]);
            __nv_bfloat16 bl = __float2bfloat16(bv0[j] - __bfloat162float(bh));
            Bh[buf][bn4 + j][bk] = bh;
            Bl[buf][bn4 + j][bk] = bl;
            bh = __float2bfloat16(bv1[j]);
            bl = __float2bfloat16(bv1[j] - __bfloat162float(bh));
            Bh[buf][bn4 + j][bk + 8] = bh;
            Bl[buf][bn4 + j][bk + 8] = bl;
        }
    };

    storeTile(0);
    __syncthreads();

    for (int t = 0; t < T; t++) {
        const int cur = t & 1;
        const bool more = (t + 1 < T);
        float4 nA0, nA1, nB0, nB1, nos, nob;
        if (more) {
            nA0 = *(const float4*)(Aptr0 + (t + 1) * 16);
            nA1 = *(const float4*)(Aptr1 + (t + 1) * 16);
            nB0 = *(const float4*)(Bptr0 + (size_t)(t + 1) * 16 * N);
            nB1 = *(const float4*)(Bptr1 + (size_t)(t + 1) * 16 * N);
            if (MODE == 2) {
                nos = *(const float4*)(os + (t + 1) * 16 + ak4);
                nob = *(const float4*)(ob + (t + 1) * 16 + ak4);
            }
        }

        uint32_t aFh[2][4], aFl[2][4], bFh[4][2], bFl[4][2];
#pragma unroll
        for (int mt = 0; mt < 2; mt++) {
            int r = m0 + 16 * mt + lr;
            aFh[mt][0] = Ah[cur][r][lc];     aFh[mt][1] = Ah[cur][r + 8][lc];
            aFh[mt][2] = Ah[cur][r][lc + 4]; aFh[mt][3] = Ah[cur][r + 8][lc + 4];
            aFl[mt][0] = Al[cur][r][lc];     aFl[mt][1] = Al[cur][r + 8][lc];
            aFl[mt][2] = Al[cur][r][lc + 4]; aFl[mt][3] = Al[cur][r + 8][lc + 4];
        }
#pragma unroll
        for (int nt = 0; nt < 4; nt++) {
            int n = n0 + 8 * nt + lr;
            bFh[nt][0] = *(const uint32_t*)&Bh[cur][n][2 * lc];
            bFh[nt][1] = *(const uint32_t*)&Bh[cur][n][2 * lc + 8];
            bFl[nt][0] = *(const uint32_t*)&Bl[cur][n][2 * lc];
            bFl[nt][1] = *(const uint32_t*)&Bl[cur][n][2 * lc + 8];
        }

        // ---- first half: mt=0 mmas ----
#pragma unroll
        for (int nt = 0; nt < 4; nt++) {
            mma_bf16(acc[0][nt], aFh[0], bFh[nt]);
            mma_bf16(acc[0][nt], aFh[0], bFl[nt]);
            mma_bf16(acc[0][nt], aFl[0], bFh[nt]);
        }

        // ---- store next tile: STS drain overlaps second mma half ----
        if (more) {
            aReg0 = nA0; aReg1 = nA1; bReg0 = nB0; bReg1 = nB1;
            if (MODE == 2) { osv = nos; obv = nob; }
            storeTile(cur ^ 1);
        }

        // ---- second half: mt=1 mmas ----
#pragma unroll
        for (int nt = 0; nt < 4; nt++) {
            mma_bf16(acc[1][nt], aFh[1], bFh[nt]);
            mma_bf16(acc[1][nt], aFh[1], bFl[nt]);
            mma_bf16(acc[1][nt], aFl[1], bFh[nt]);
        }

        __syncthreads();
    }

    // ------------------ epilogue ------------------
    if (MODE == 1) {
        const int region = blockN / DMODEL;   // 0=q, 1=k, 2=v
        if (region < 2) {
            float mean[2][2], rstd[2][2];
#pragma unroll
            for (int mt = 0; mt < 2; mt++)
#pragma unroll
                for (int hf = 0; hf < 2; hf++) {
                    float s = 0.f, q = 0.f;
#pragma unroll
                    for (int nt = 0; nt < 4; nt++) {
                        float v0 = acc[mt][nt][2 * hf], v1 = acc[mt][nt][2 * hf + 1];
                        s += v0 + v1;
                        q += v0 * v0 + v1 * v1;
                    }
                    s += __shfl_xor_sync(0xffffffff, s, 1);
                    s += __shfl_xor_sync(0xffffffff, s, 2);
                    q += __shfl_xor_sync(0xffffffff, q, 1);
                    q += __shfl_xor_sync(0xffffffff, q, 2);
                    if (lc == 0)
                        red[m0 + 16 * mt + 8 * hf + lr][wn] = make_float2(s, q);
                }
            __syncthreads();
#pragma unroll
            for (int mt = 0; mt < 2; mt++)
#pragma unroll
                for (int hf = 0; hf < 2; hf++) {
                    float2 r0 = red[m0 + 16 * mt + 8 * hf + lr][0];
                    float2 r1 = red[m0 + 16 * mt + 8 * hf + lr][1];
                    float s = r0.x + r1.x, q = r0.y + r1.y;
                    float mn = s * (1.0f / 64.0f);
                    float vr = q * (1.0f / 64.0f) - mn * mn;
                    mean[mt][hf] = mn;
                    rstd[mt][hf] = rsqrtf(vr + 1e-6f);
                }

            const float* sc = region ? ks : qs;
            const float* bi = region ? kb : qb;
            const float mul = region ? 1.0f : 0.125f;

#pragma unroll
            for (int mt = 0; mt < 2; mt++) {
#pragma unroll
                for (int nt = 0; nt < 4; nt++) {
                    int c = n0 + 8 * nt + 2 * lc;
                    float s0 = sc[c] * mul, s1 = sc[c + 1] * mul;
                    float b0 = bi[c] * mul, b1 = bi[c + 1] * mul;
                    int row = blockM + m0 + 16 * mt + lr;
                    int col = blockN + c;
                    float2 v0 = { (acc[mt][nt][0] - mean[mt][0]) * rstd[mt][0] * s0 + b0,
                                  (acc[mt][nt][1] - mean[mt][0]) * rstd[mt][0] * s1 + b1 };
                    float2 v1 = { (acc[mt][nt][2] - mean[mt][1]) * rstd[mt][1] * s0 + b0,
                                  (acc[mt][nt][3] - mean[mt][1]) * rstd[mt][1] * s1 + b1 };
                    *(float2*)(C + (size_t)row * N + col)       = v0;
                    *(float2*)(C + (size_t)(row + 8) * N + col) = v1;
                }
            }
            return;
        }
#pragma unroll
        for (int mt = 0; mt < 2; mt++) {
#pragma unroll
            for (int nt = 0; nt < 4; nt++) {
                int row = blockM + m0 + 16 * mt + lr;
                int col = blockN + n0 + 8 * nt + 2 * lc;
                float2 v0 = { acc[mt][nt][0], acc[mt][nt][1] };
                float2 v1 = { acc[mt][nt][2], acc[mt][nt][3] };
                *(float2*)(C + (size_t)row * N + col)       = v0;
                *(float2*)(C + (size_t)(row + 8) * N + col) = v1;
            }
        }
        return;
    }

#pragma unroll
    for (int mt = 0; mt < 2; mt++) {
#pragma unroll
        for (int nt = 0; nt < 4; nt++) {
            int row = blockM + m0 + 16 * mt + lr;
            int col = blockN + n0 + 8 * nt + 2 * lc;
            float b0 = bias[col], b1 = bias[col + 1];
            float2 v0 = { acc[mt][nt][0] + b0, acc[mt][nt][1] + b1 };
            float2 v1 = { acc[mt][nt][2] + b0, acc[mt][nt][3] + b1 };
            *(float2*)(C + (size_t)row * N + col)       = v0;
            *(float2*)(C + (size_t)(row + 8) * N + col) = v1;
        }
    }
}

// =========================================================================
// Tensor-core flash attention (bf16x3) — the proven v2, verbatim. FROZEN.
// =========================================================================
#define KS 36

__global__ void __launch_bounds__(256) flash_mma_kernel(const float* __restrict__ qkv,
                                                        float* __restrict__ out)
{
    __shared__ uint32_t Kh[64][KS];
    __shared__ uint32_t Kl[64][KS];
    __shared__ uint32_t Vh[64][KS];   // transposed: [d][keypair], col swizzled
    __shared__ uint32_t Vl[64][KS];

    const int bh = blockIdx.y;
    const int b = bh / NHEAD, h = bh % NHEAD;
    const int q0 = blockIdx.x * 128;
    const int tid = threadIdx.x;
    const int lane = tid & 31;
    const int wid = tid >> 5;
    const int lr = lane >> 2;
    const int lc = lane & 3;

    uint32_t qh[4][4], ql[4][4];
    {
        const float* qb_ = qkv + (size_t)(b * SEQ + q0 + wid * 16) * TD + h * HD;
#pragma unroll
        for (int kt = 0; kt < 4; kt++) {
            int d = kt * 16 + 2 * lc;
            split_pack(qb_[(size_t)lr * TD + d],       qb_[(size_t)lr * TD + d + 1],       qh[kt][0], ql[kt][0]);
            split_pack(qb_[(size_t)(lr + 8) * TD + d], qb_[(size_t)(lr + 8) * TD + d + 1], qh[kt][1], ql[kt][1]);
            split_pack(qb_[(size_t)lr * TD + d + 8],       qb_[(size_t)lr * TD + d + 9],       qh[kt][2], ql[kt][2]);
            split_pack(qb_[(size_t)(lr + 8) * TD + d + 8], qb_[(size_t)(lr + 8) * TD + d + 9], qh[kt][3], ql[kt][3]);
        }
    }

    float o[8][4];
#pragma unroll
    for (int i = 0; i < 8; i++)
#pragma unroll
        for (int j = 0; j < 4; j++) o[i][j] = 0.f;
    float m0 = -INFINITY, m1 = -INFINITY, l0 = 0.f, l1 = 0.f;

    for (int jt = 0; jt < SEQ / 64; jt++) {
        __syncthreads();
        const float* kptr = qkv + (size_t)(b * SEQ + jt * 64) * TD + DMODEL + h * HD;
        const float* vptr = kptr + DMODEL;

#pragma unroll
        for (int i = 0; i < 8; i++) {
            int item = tid + i * 256;
            int key = item >> 5, dp = item & 31;
            float2 v = *(const float2*)(kptr + (size_t)key * TD + 2 * dp);
            uint32_t hh, ll;
            split_pack(v.x, v.y, hh, ll);
            Kh[key][dp] = hh; Kl[key][dp] = ll;
        }

#pragma unroll
        for (int r = 0; r < 4; r++) {
            int j = wid + 8 * r;
            const float* v0p = vptr + (size_t)(2 * j) * TD + 2 * lane;
            float2 a = *(const float2*)v0p;
            float2 c = *(const float2*)(v0p + TD);
            int d0 = 2 * lane;
            int jc = (j & ~7) | ((j & 7) ^ (lane & 7));
            uint32_t hh, ll;
            split_pack(a.x, c.x, hh, ll);
            Vh[d0][jc] = hh; Vl[d0][jc] = ll;
            split_pack(a.y, c.y, hh, ll);
            Vh[d0 + 1][jc] = hh; Vl[d0 + 1][jc] = ll;
        }
        __syncthreads();

        float s[8][4];
#pragma unroll
        for (int nt = 0; nt < 8; nt++) {
            float c[4] = {0.f, 0.f, 0.f, 0.f};
#pragma unroll
            for (int kt = 0; kt < 4; kt++) {
                int krow = 8 * nt + lr;
                uint32_t bhf[2] = { Kh[krow][8 * kt + lc], Kh[krow][8 * kt + 4 + lc] };
                uint32_t blf[2] = { Kl[krow][8 * kt + lc], Kl[krow][8 * kt + 4 + lc] };
                mma_bf16(c, qh[kt], bhf);
                mma_bf16(c, qh[kt], blf);
                mma_bf16(c, ql[kt], bhf);
            }
            s[nt][0] = c[0]; s[nt][1] = c[1]; s[nt][2] = c[2]; s[nt][3] = c[3];
        }

        float rmax0 = -INFINITY, rmax1 = -INFINITY;
#pragma unroll
        for (int nt = 0; nt < 8; nt++) {
            rmax0 = fmaxf(rmax0, fmaxf(s[nt][0], s[nt][1]));
            rmax1 = fmaxf(rmax1, fmaxf(s[nt][2], s[nt][3]));
        }
        rmax0 = fmaxf(rmax0, __shfl_xor_sync(0xffffffff, rmax0, 1));
        rmax0 = fmaxf(rmax0, __shfl_xor_sync(0xffffffff, rmax0, 2));
        rmax1 = fmaxf(rmax1, __shfl_xor_sync(0xffffffff, rmax1, 1));
        rmax1 = fmaxf(rmax1, __shfl_xor_sync(0xffffffff, rmax1, 2));

        float mn0 = fmaxf(m0, rmax0), mn1 = fmaxf(m1, rmax1);
        float sc0 = __expf(m0 - mn0), sc1 = __expf(m1 - mn1);
        l0 *= sc0; l1 *= sc1;
        m0 = mn0; m1 = mn1;
#pragma unroll
        for (int nt = 0; nt < 8; nt++) {
            o[nt][0] *= sc0; o[nt][1] *= sc0;
            o[nt][2] *= sc1; o[nt][3] *= sc1;
        }

        uint32_t Ph0[8], Ph1[8], Pl0[8], Pl1[8];
        float ps0 = 0.f, ps1 = 0.f;
#pragma unroll
        for (int nt = 0; nt < 8; nt++) {
            float p0 = __expf(s[nt][0] - mn0);
            float p1 = __expf(s[nt][1] - mn0);
            float p2 = __expf(s[nt][2] - mn1);
            float p3 = __expf(s[nt][3] - mn1);
            ps0 += p0 + p1; ps1 += p2 + p3;
            split_pack(p0, p1, Ph0[nt], Pl0[nt]);
            split_pack(p2, p3, Ph1[nt], Pl1[nt]);
        }
        ps0 += __shfl_xor_sync(0xffffffff, ps0, 1);
        ps0 += __shfl_xor_sync(0xffffffff, ps0, 2);
        ps1 += __shfl_xor_sync(0xffffffff, ps1, 1);
        ps1 += __shfl_xor_sync(0xffffffff, ps1, 2);
        l0 += ps0; l1 += ps1;

#pragma unroll
        for (int nt = 0; nt < 8; nt++) {
            int drow = 8 * nt + lr;
            int xsw = (drow >> 1) & 7;
#pragma unroll
            for (int kt = 0; kt < 4; kt++) {
                uint32_t ah[4] = { Ph0[2 * kt], Ph1[2 * kt], Ph0[2 * kt + 1], Ph1[2 * kt + 1] };
                uint32_t al[4] = { Pl0[2 * kt], Pl1[2 * kt], Pl0[2 * kt + 1], Pl1[2 * kt + 1] };
                int jc0 = 8 * kt + (lc ^ xsw);
                int jc1 = 8 * kt + ((lc + 4) ^ xsw);
                uint32_t bhf[2] = { Vh[drow][jc0], Vh[drow][jc1] };
                uint32_t blf[2] = { Vl[drow][jc0], Vl[drow][jc1] };
                mma_bf16(o[nt], ah, bhf);
                mma_bf16(o[nt], ah, blf);
                mma_bf16(o[nt], al, bhf);
            }
        }
    }

    const float inv0 = 1.0f / l0, inv1 = 1.0f / l1;
    const int row0 = b * SEQ + q0 + wid * 16 + lr;
#pragma unroll
    for (int nt = 0; nt < 8; nt++) {
        int col = h * HD + 8 * nt + 2 * lc;
        float2 v0 = { o[nt][0] * inv0, o[nt][1] * inv0 };
        float2 v1 = { o[nt][2] * inv1, o[nt][3] * inv1 };
        *(float2*)(out + (size_t)row0 * DMODEL + col)       = v0;
        *(float2*)(out + (size_t)(row0 + 8) * DMODEL + col) = v1;
    }
}

// ---------------- LayerNorm stats (mean, rstd) per token row --------------
__global__ void __launch_bounds__(256) ln_stats_kernel(const float* __restrict__ in,
                                                       float2* __restrict__ st)
{
    const int warp = (blockIdx.x * blockDim.x + threadIdx.x) >> 5;
    const int lane = threadIdx.x & 31;
    if (warp >= TOK) return;

    const float4* row = (const float4*)(in + (size_t)warp * DMODEL);
    float s = 0.f, q = 0.f;
#pragma unroll
    for (int i = 0; i < 6; i++) {
        float4 v = row[lane + 32 * i];
        s += v.x + v.y + v.z + v.w;
        q += v.x * v.x + v.y * v.y + v.z * v.z + v.w * v.w;
    }
#pragma unroll
    for (int off = 16; off > 0; off >>= 1) {
        s += __shfl_xor_sync(0xffffffff, s, off);
        q += __shfl_xor_sync(0xffffffff, q, off);
    }
    if (lane == 0) {
        float mn = s * (1.0f / DMODEL);
        float vr = q * (1.0f / DMODEL) - mn * mn;
        st[warp] = make_float2(mn, rsqrtf(vr + 1e-6f));
    }
}

// ---------------- launcher -----------------------------------------------
extern "C" void kernel_launch(void* const* d_in, const int* in_sizes, int n_in,
                              void* d_out, int out_size)
{
    const float* x     = (const float*)d_in[0];
    const float* W_qkv = (const float*)d_in[1];
    const float* qs    = (const float*)d_in[2];
    const float* qb    = (const float*)d_in[3];
    const float* ks    = (const float*)d_in[4];
    const float* kb    = (const float*)d_in[5];
    const float* os    = (const float*)d_in[6];
    const float* ob    = (const float*)d_in[7];
    const float* W_out = (const float*)d_in[8];
    const float* b_out = (const float*)d_in[9];
    float* out = (float*)d_out;

    float *qkv_ptr, *attn_ptr;
    float2* stat_ptr;
    cudaGetSymbolAddress((void**)&qkv_ptr, g_qkv);
    cudaGetSymbolAddress((void**)&attn_ptr, g_attn);
    cudaGetSymbolAddress((void**)&stat_ptr, g_stat);

    // 1. QKV projection + fused per-head QK LayerNorm (+0.125 q scale)
    gemm_fused_kernel<1><<<dim3(TD / 64, TOK / 64), 128>>>(
        x, W_qkv, nullptr, qkv_ptr, TOK, TD, DMODEL,
        qs, qb, ks, kb, nullptr, nullptr, nullptr);

    // 2. attention (tensor-core flash v2 — frozen)
    flash_mma_kernel<<<dim3(SEQ / 128, NBATCH * NHEAD), 256>>>(qkv_ptr, attn_ptr);

    // 3. output LayerNorm stats
    ln_stats_kernel<<<TOK / 8, 256>>>(attn_ptr, stat_ptr);

    // 4. final projection with fused LN on A + bias
    gemm_fused_kernel<2><<<dim3(DMODEL / 64, TOK / 64), 128>>>(
        attn_ptr, W_out, b_out, out, TOK, DMODEL, DMODEL,
        nullptr, nullptr, nullptr, nullptr, stat_ptr, os, ob);
}

// round 15
// speedup vs baseline: 1.1780x; 1.1780x over previous
#include <cuda_runtime.h>
#include <cuda_bf16.h>
#include <stdint.h>
#include <math.h>

#define TOK   4096      // B*P
#define DMODEL 768
#define TD    2304      // 3*D
#define NHEAD 12
#define HD    64
#define SEQ   2048
#define NBATCH 2

// ---------------- scratch (no allocations allowed) ----------------
__device__ float  g_qkv[TOK * TD];      // [token, 3*D]
__device__ float  g_attn[TOK * DMODEL]; // attention output, pre-LN
__device__ float2 g_psum[TOK * NHEAD];  // per-(token,head) partial (sum, sumsq)
__device__ float2 g_stat[TOK];          // (mean, rstd) of attention output rows

__device__ __forceinline__ void mma_bf16(float c[4], const uint32_t a[4], const uint32_t b[2])
{
    asm volatile(
        "mma.sync.aligned.m16n8k16.row.col.f32.bf16.bf16.f32 "
        "{%0,%1,%2,%3}, {%4,%5,%6,%7}, {%8,%9}, {%0,%1,%2,%3};"
        : "+f"(c[0]), "+f"(c[1]), "+f"(c[2]), "+f"(c[3])
        : "r"(a[0]), "r"(a[1]), "r"(a[2]), "r"(a[3]), "r"(b[0]), "r"(b[1]));
}

__device__ __forceinline__ void split_pack(float x0, float x1, uint32_t& hi, uint32_t& lo)
{
    __nv_bfloat16 h0 = __float2bfloat16(x0);
    __nv_bfloat16 h1 = __float2bfloat16(x1);
    __nv_bfloat16 l0 = __float2bfloat16(x0 - __bfloat162float(h0));
    __nv_bfloat16 l1 = __float2bfloat16(x1 - __bfloat162float(h1));
    hi = ((uint32_t)__bfloat16_as_ushort(h1) << 16) | (uint32_t)__bfloat16_as_ushort(h0);
    lo = ((uint32_t)__bfloat16_as_ushort(l1) << 16) | (uint32_t)__bfloat16_as_ushort(l0);
}

// =========================================================================
// bf16x3 tensor-core GEMM — the R12 661.6us kernel, verbatim.
// 128x64 block, 256 threads, double-buffered, sandwich STS schedule.
//  MODE 1: QKV proj + fused per-head QK LayerNorm (+0.125 q). v plain.
//  MODE 2: out proj, A-load applies LN via precomputed stats, + bias.
// =========================================================================
#define SA 12
#define SB 24

template<int MODE>
__global__ void __launch_bounds__(256) gemm_fused_kernel(
    const float* __restrict__ A, const float* __restrict__ B,
    const float* __restrict__ bias, float* __restrict__ C,
    int M, int N, int K,
    const float* __restrict__ qs, const float* __restrict__ qb,
    const float* __restrict__ ks, const float* __restrict__ kb,
    const float2* __restrict__ lnstat,
    const float* __restrict__ os, const float* __restrict__ ob)
{
    __shared__ uint32_t Ah[2][128][SA];
    __shared__ uint32_t Al[2][128][SA];
    __shared__ __nv_bfloat16 Bh[2][64][SB];
    __shared__ __nv_bfloat16 Bl[2][64][SB];
    __shared__ float2 red[128][2];

    const int tid  = threadIdx.x;
    const int lane = tid & 31;
    const int wid  = tid >> 5;
    const int wm   = wid & 3;
    const int wn   = wid >> 2;
    const int m0   = wm * 32;
    const int n0   = wn * 32;
    const int lr   = lane >> 2;
    const int lc   = lane & 3;

    const int blockM = blockIdx.y * 128;
    const int blockN = blockIdx.x * 64;

    const int am0 = tid >> 2;
    const int ak4 = (tid & 3) * 4;
    const float* Aptr0 = A + (size_t)(blockM + am0) * K + ak4;
    const float* Aptr1 = A + (size_t)(blockM + am0 + 64) * K + ak4;
    const int bk  = tid >> 4;
    const int bn4 = (tid & 15) * 4;
    const float* Bptr = B + (size_t)bk * N + blockN + bn4;

    float2 st0 = make_float2(0.f, 1.f), st1 = st0;
    if (MODE == 2) {
        st0 = lnstat[blockM + am0];
        st1 = lnstat[blockM + am0 + 64];
    }

    float acc[2][4][4];
#pragma unroll
    for (int i = 0; i < 2; i++)
#pragma unroll
        for (int j = 0; j < 4; j++)
#pragma unroll
            for (int k = 0; k < 4; k++) acc[i][j][k] = 0.f;

    const int T = K / 16;

    float4 aReg0 = *(const float4*)Aptr0;
    float4 aReg1 = *(const float4*)Aptr1;
    float4 bReg  = *(const float4*)Bptr;
    float4 osv = make_float4(1,1,1,1), obv = make_float4(0,0,0,0);
    if (MODE == 2) {
        osv = *(const float4*)(os + ak4);
        obv = *(const float4*)(ob + ak4);
    }

    auto storeTile = [&](int buf) {
        float4 a0 = aReg0, a1 = aReg1;
        if (MODE == 2) {
            a0.x = (a0.x - st0.x) * st0.y * osv.x + obv.x;
            a0.y = (a0.y - st0.x) * st0.y * osv.y + obv.y;
            a0.z = (a0.z - st0.x) * st0.y * osv.z + obv.z;
            a0.w = (a0.w - st0.x) * st0.y * osv.w + obv.w;
            a1.x = (a1.x - st1.x) * st1.y * osv.x + obv.x;
            a1.y = (a1.y - st1.x) * st1.y * osv.y + obv.y;
            a1.z = (a1.z - st1.x) * st1.y * osv.z + obv.z;
            a1.w = (a1.w - st1.x) * st1.y * osv.w + obv.w;
        }
        uint32_t h, l;
        split_pack(a0.x, a0.y, h, l);
        Ah[buf][am0][ak4 / 2] = h; Al[buf][am0][ak4 / 2] = l;
        split_pack(a0.z, a0.w, h, l);
        Ah[buf][am0][ak4 / 2 + 1] = h; Al[buf][am0][ak4 / 2 + 1] = l;
        split_pack(a1.x, a1.y, h, l);
        Ah[buf][am0 + 64][ak4 / 2] = h; Al[buf][am0 + 64][ak4 / 2] = l;
        split_pack(a1.z, a1.w, h, l);
        Ah[buf][am0 + 64][ak4 / 2 + 1] = h; Al[buf][am0 + 64][ak4 / 2 + 1] = l;

        const float bv[4] = { bReg.x, bReg.y, bReg.z, bReg.w };
#pragma unroll
        for (int j = 0; j < 4; j++) {
            __nv_bfloat16 bh = __float2bfloat16(bv[j]);
            __nv_bfloat16 bl = __float2bfloat16(bv[j] - __bfloat162float(bh));
            Bh[buf][bn4 + j][bk] = bh;
            Bl[buf][bn4 + j][bk] = bl;
        }
    };

    storeTile(0);
    __syncthreads();

    for (int t = 0; t < T; t++) {
        const int cur = t & 1;
        const bool more = (t + 1 < T);
        float4 nA0, nA1, nB, nos, nob;
        if (more) {
            nA0 = *(const float4*)(Aptr0 + (t + 1) * 16);
            nA1 = *(const float4*)(Aptr1 + (t + 1) * 16);
            nB  = *(const float4*)(Bptr + (size_t)(t + 1) * 16 * N);
            if (MODE == 2) {
                nos = *(const float4*)(os + (t + 1) * 16 + ak4);
                nob = *(const float4*)(ob + (t + 1) * 16 + ak4);
            }
        }

        uint32_t aFh[2][4], aFl[2][4], bFh[4][2], bFl[4][2];
#pragma unroll
        for (int mt = 0; mt < 2; mt++) {
            int r = m0 + 16 * mt + lr;
            aFh[mt][0] = Ah[cur][r][lc];     aFh[mt][1] = Ah[cur][r + 8][lc];
            aFh[mt][2] = Ah[cur][r][lc + 4]; aFh[mt][3] = Ah[cur][r + 8][lc + 4];
            aFl[mt][0] = Al[cur][r][lc];     aFl[mt][1] = Al[cur][r + 8][lc];
            aFl[mt][2] = Al[cur][r][lc + 4]; aFl[mt][3] = Al[cur][r + 8][lc + 4];
        }
#pragma unroll
        for (int nt = 0; nt < 4; nt++) {
            int n = n0 + 8 * nt + lr;
            bFh[nt][0] = *(const uint32_t*)&Bh[cur][n][2 * lc];
            bFh[nt][1] = *(const uint32_t*)&Bh[cur][n][2 * lc + 8];
            bFl[nt][0] = *(const uint32_t*)&Bl[cur][n][2 * lc];
            bFl[nt][1] = *(const uint32_t*)&Bl[cur][n][2 * lc + 8];
        }

        // ---- first half: mt=0 mmas ----
#pragma unroll
        for (int nt = 0; nt < 4; nt++) {
            mma_bf16(acc[0][nt], aFh[0], bFh[nt]);
            mma_bf16(acc[0][nt], aFh[0], bFl[nt]);
            mma_bf16(acc[0][nt], aFl[0], bFh[nt]);
        }

        // ---- store next tile: STS drain overlaps second mma half ----
        if (more) {
            aReg0 = nA0; aReg1 = nA1; bReg = nB;
            if (MODE == 2) { osv = nos; obv = nob; }
            storeTile(cur ^ 1);
        }

        // ---- second half: mt=1 mmas ----
#pragma unroll
        for (int nt = 0; nt < 4; nt++) {
            mma_bf16(acc[1][nt], aFh[1], bFh[nt]);
            mma_bf16(acc[1][nt], aFh[1], bFl[nt]);
            mma_bf16(acc[1][nt], aFl[1], bFh[nt]);
        }

        __syncthreads();
    }

    // ------------------ epilogue ------------------
    if (MODE == 1) {
        const int region = blockN / DMODEL;   // 0=q, 1=k, 2=v
        if (region < 2) {
            float mean[2][2], rstd[2][2];
#pragma unroll
            for (int mt = 0; mt < 2; mt++)
#pragma unroll
                for (int hf = 0; hf < 2; hf++) {
                    float s = 0.f, q = 0.f;
#pragma unroll
                    for (int nt = 0; nt < 4; nt++) {
                        float v0 = acc[mt][nt][2 * hf], v1 = acc[mt][nt][2 * hf + 1];
                        s += v0 + v1;
                        q += v0 * v0 + v1 * v1;
                    }
                    s += __shfl_xor_sync(0xffffffff, s, 1);
                    s += __shfl_xor_sync(0xffffffff, s, 2);
                    q += __shfl_xor_sync(0xffffffff, q, 1);
                    q += __shfl_xor_sync(0xffffffff, q, 2);
                    if (lc == 0)
                        red[m0 + 16 * mt + 8 * hf + lr][wn] = make_float2(s, q);
                }
            __syncthreads();
#pragma unroll
            for (int mt = 0; mt < 2; mt++)
#pragma unroll
                for (int hf = 0; hf < 2; hf++) {
                    float2 r0 = red[m0 + 16 * mt + 8 * hf + lr][0];
                    float2 r1 = red[m0 + 16 * mt + 8 * hf + lr][1];
                    float s = r0.x + r1.x, q = r0.y + r1.y;
                    float mn = s * (1.0f / 64.0f);
                    float vr = q * (1.0f / 64.0f) - mn * mn;
                    mean[mt][hf] = mn;
                    rstd[mt][hf] = rsqrtf(vr + 1e-6f);
                }

            const float* sc = region ? ks : qs;
            const float* bi = region ? kb : qb;
            const float mul = region ? 1.0f : 0.125f;

#pragma unroll
            for (int mt = 0; mt < 2; mt++) {
#pragma unroll
                for (int nt = 0; nt < 4; nt++) {
                    int c = n0 + 8 * nt + 2 * lc;
                    float s0 = sc[c] * mul, s1 = sc[c + 1] * mul;
                    float b0 = bi[c] * mul, b1 = bi[c + 1] * mul;
                    int row = blockM + m0 + 16 * mt + lr;
                    int col = blockN + c;
                    float2 v0 = { (acc[mt][nt][0] - mean[mt][0]) * rstd[mt][0] * s0 + b0,
                                  (acc[mt][nt][1] - mean[mt][0]) * rstd[mt][0] * s1 + b1 };
                    float2 v1 = { (acc[mt][nt][2] - mean[mt][1]) * rstd[mt][1] * s0 + b0,
                                  (acc[mt][nt][3] - mean[mt][1]) * rstd[mt][1] * s1 + b1 };
                    *(float2*)(C + (size_t)row * N + col)       = v0;
                    *(float2*)(C + (size_t)(row + 8) * N + col) = v1;
                }
            }
            return;
        }
#pragma unroll
        for (int mt = 0; mt < 2; mt++) {
#pragma unroll
            for (int nt = 0; nt < 4; nt++) {
                int row = blockM + m0 + 16 * mt + lr;
                int col = blockN + n0 + 8 * nt + 2 * lc;
                float2 v0 = { acc[mt][nt][0], acc[mt][nt][1] };
                float2 v1 = { acc[mt][nt][2], acc[mt][nt][3] };
                *(float2*)(C + (size_t)row * N + col)       = v0;
                *(float2*)(C + (size_t)(row + 8) * N + col) = v1;
            }
        }
        return;
    }

#pragma unroll
    for (int mt = 0; mt < 2; mt++) {
#pragma unroll
        for (int nt = 0; nt < 4; nt++) {
            int row = blockM + m0 + 16 * mt + lr;
            int col = blockN + n0 + 8 * nt + 2 * lc;
            float b0 = bias[col], b1 = bias[col + 1];
            float2 v0 = { acc[mt][nt][0] + b0, acc[mt][nt][1] + b1 };
            float2 v1 = { acc[mt][nt][2] + b0, acc[mt][nt][3] + b1 };
            *(float2*)(C + (size_t)row * N + col)       = v0;
            *(float2*)(C + (size_t)(row + 8) * N + col) = v1;
        }
    }
}

// =========================================================================
// Tensor-core flash attention (bf16x3) — proven v2 main loop, FROZEN.
// Only the epilogue is extended: per-(token,head) partial LN sums are
// written to g_psum so ln-stats needn't re-read the 12.6MB attn tensor.
// =========================================================================
#define KS 36

__global__ void __launch_bounds__(256) flash_mma_kernel(const float* __restrict__ qkv,
                                                        float* __restrict__ out,
                                                        float2* __restrict__ psum)
{
    __shared__ uint32_t Kh[64][KS];
    __shared__ uint32_t Kl[64][KS];
    __shared__ uint32_t Vh[64][KS];   // transposed: [d][keypair], col swizzled
    __shared__ uint32_t Vl[64][KS];

    const int bh = blockIdx.y;
    const int b = bh / NHEAD, h = bh % NHEAD;
    const int q0 = blockIdx.x * 128;
    const int tid = threadIdx.x;
    const int lane = tid & 31;
    const int wid = tid >> 5;
    const int lr = lane >> 2;
    const int lc = lane & 3;

    uint32_t qh[4][4], ql[4][4];
    {
        const float* qb_ = qkv + (size_t)(b * SEQ + q0 + wid * 16) * TD + h * HD;
#pragma unroll
        for (int kt = 0; kt < 4; kt++) {
            int d = kt * 16 + 2 * lc;
            split_pack(qb_[(size_t)lr * TD + d],       qb_[(size_t)lr * TD + d + 1],       qh[kt][0], ql[kt][0]);
            split_pack(qb_[(size_t)(lr + 8) * TD + d], qb_[(size_t)(lr + 8) * TD + d + 1], qh[kt][1], ql[kt][1]);
            split_pack(qb_[(size_t)lr * TD + d + 8],       qb_[(size_t)lr * TD + d + 9],       qh[kt][2], ql[kt][2]);
            split_pack(qb_[(size_t)(lr + 8) * TD + d + 8], qb_[(size_t)(lr + 8) * TD + d + 9], qh[kt][3], ql[kt][3]);
        }
    }

    float o[8][4];
#pragma unroll
    for (int i = 0; i < 8; i++)
#pragma unroll
        for (int j = 0; j < 4; j++) o[i][j] = 0.f;
    float m0 = -INFINITY, m1 = -INFINITY, l0 = 0.f, l1 = 0.f;

    for (int jt = 0; jt < SEQ / 64; jt++) {
        __syncthreads();
        const float* kptr = qkv + (size_t)(b * SEQ + jt * 64) * TD + DMODEL + h * HD;
        const float* vptr = kptr + DMODEL;

#pragma unroll
        for (int i = 0; i < 8; i++) {
            int item = tid + i * 256;
            int key = item >> 5, dp = item & 31;
            float2 v = *(const float2*)(kptr + (size_t)key * TD + 2 * dp);
            uint32_t hh, ll;
            split_pack(v.x, v.y, hh, ll);
            Kh[key][dp] = hh; Kl[key][dp] = ll;
        }

#pragma unroll
        for (int r = 0; r < 4; r++) {
            int j = wid + 8 * r;
            const float* v0p = vptr + (size_t)(2 * j) * TD + 2 * lane;
            float2 a = *(const float2*)v0p;
            float2 c = *(const float2*)(v0p + TD);
            int d0 = 2 * lane;
            int jc = (j & ~7) | ((j & 7) ^ (lane & 7));
            uint32_t hh, ll;
            split_pack(a.x, c.x, hh, ll);
            Vh[d0][jc] = hh; Vl[d0][jc] = ll;
            split_pack(a.y, c.y, hh, ll);
            Vh[d0 + 1][jc] = hh; Vl[d0 + 1][jc] = ll;
        }
        __syncthreads();

        float s[8][4];
#pragma unroll
        for (int nt = 0; nt < 8; nt++) {
            float c[4] = {0.f, 0.f, 0.f, 0.f};
#pragma unroll
            for (int kt = 0; kt < 4; kt++) {
                int krow = 8 * nt + lr;
                uint32_t bhf[2] = { Kh[krow][8 * kt + lc], Kh[krow][8 * kt + 4 + lc] };
                uint32_t blf[2] = { Kl[krow][8 * kt + lc], Kl[krow][8 * kt + 4 + lc] };
                mma_bf16(c, qh[kt], bhf);
                mma_bf16(c, qh[kt], blf);
                mma_bf16(c, ql[kt], bhf);
            }
            s[nt][0] = c[0]; s[nt][1] = c[1]; s[nt][2] = c[2]; s[nt][3] = c[3];
        }

        float rmax0 = -INFINITY, rmax1 = -INFINITY;
#pragma unroll
        for (int nt = 0; nt < 8; nt++) {
            rmax0 = fmaxf(rmax0, fmaxf(s[nt][0], s[nt][1]));
            rmax1 = fmaxf(rmax1, fmaxf(s[nt][2], s[nt][3]));
        }
        rmax0 = fmaxf(rmax0, __shfl_xor_sync(0xffffffff, rmax0, 1));
        rmax0 = fmaxf(rmax0, __shfl_xor_sync(0xffffffff, rmax0, 2));
        rmax1 = fmaxf(rmax1, __shfl_xor_sync(0xffffffff, rmax1, 1));
        rmax1 = fmaxf(rmax1, __shfl_xor_sync(0xffffffff, rmax1, 2));

        float mn0 = fmaxf(m0, rmax0), mn1 = fmaxf(m1, rmax1);
        float sc0 = __expf(m0 - mn0), sc1 = __expf(m1 - mn1);
        l0 *= sc0; l1 *= sc1;
        m0 = mn0; m1 = mn1;
#pragma unroll
        for (int nt = 0; nt < 8; nt++) {
            o[nt][0] *= sc0; o[nt][1] *= sc0;
            o[nt][2] *= sc1; o[nt][3] *= sc1;
        }

        uint32_t Ph0[8], Ph1[8], Pl0[8], Pl1[8];
        float ps0 = 0.f, ps1 = 0.f;
#pragma unroll
        for (int nt = 0; nt < 8; nt++) {
            float p0 = __expf(s[nt][0] - mn0);
            float p1 = __expf(s[nt][1] - mn0);
            float p2 = __expf(s[nt][2] - mn1);
            float p3 = __expf(s[nt][3] - mn1);
            ps0 += p0 + p1; ps1 += p2 + p3;
            split_pack(p0, p1, Ph0[nt], Pl0[nt]);
            split_pack(p2, p3, Ph1[nt], Pl1[nt]);
        }
        ps0 += __shfl_xor_sync(0xffffffff, ps0, 1);
        ps0 += __shfl_xor_sync(0xffffffff, ps0, 2);
        ps1 += __shfl_xor_sync(0xffffffff, ps1, 1);
        ps1 += __shfl_xor_sync(0xffffffff, ps1, 2);
        l0 += ps0; l1 += ps1;

#pragma unroll
        for (int nt = 0; nt < 8; nt++) {
            int drow = 8 * nt + lr;
            int xsw = (drow >> 1) & 7;
#pragma unroll
            for (int kt = 0; kt < 4; kt++) {
                uint32_t ah[4] = { Ph0[2 * kt], Ph1[2 * kt], Ph0[2 * kt + 1], Ph1[2 * kt + 1] };
                uint32_t al[4] = { Pl0[2 * kt], Pl1[2 * kt], Pl0[2 * kt + 1], Pl1[2 * kt + 1] };
                int jc0 = 8 * kt + (lc ^ xsw);
                int jc1 = 8 * kt + ((lc + 4) ^ xsw);
                uint32_t bhf[2] = { Vh[drow][jc0], Vh[drow][jc1] };
                uint32_t blf[2] = { Vl[drow][jc0], Vl[drow][jc1] };
                mma_bf16(o[nt], ah, bhf);
                mma_bf16(o[nt], ah, blf);
                mma_bf16(o[nt], al, bhf);
            }
        }
    }

    // ---- epilogue: store outputs + per-(token,head) LN partials ----
    const float inv0 = 1.0f / l0, inv1 = 1.0f / l1;
    const int row0 = b * SEQ + q0 + wid * 16 + lr;
    float sA = 0.f, qA = 0.f, sB = 0.f, qB = 0.f;
#pragma unroll
    for (int nt = 0; nt < 8; nt++) {
        int col = h * HD + 8 * nt + 2 * lc;
        float2 v0 = { o[nt][0] * inv0, o[nt][1] * inv0 };
        float2 v1 = { o[nt][2] * inv1, o[nt][3] * inv1 };
        sA += v0.x + v0.y; qA += v0.x * v0.x + v0.y * v0.y;
        sB += v1.x + v1.y; qB += v1.x * v1.x + v1.y * v1.y;
        *(float2*)(out + (size_t)row0 * DMODEL + col)       = v0;
        *(float2*)(out + (size_t)(row0 + 8) * DMODEL + col) = v1;
    }
    sA += __shfl_xor_sync(0xffffffff, sA, 1);
    sA += __shfl_xor_sync(0xffffffff, sA, 2);
    qA += __shfl_xor_sync(0xffffffff, qA, 1);
    qA += __shfl_xor_sync(0xffffffff, qA, 2);
    sB += __shfl_xor_sync(0xffffffff, sB, 1);
    sB += __shfl_xor_sync(0xffffffff, sB, 2);
    qB += __shfl_xor_sync(0xffffffff, qB, 1);
    qB += __shfl_xor_sync(0xffffffff, qB, 2);
    if (lc == 0) {
        psum[(size_t)row0 * NHEAD + h]       = make_float2(sA, qA);
        psum[(size_t)(row0 + 8) * NHEAD + h] = make_float2(sB, qB);
    }
}

// ---------------- LN stats finalize: 12 head-partials -> (mean, rstd) ----
__global__ void __launch_bounds__(256) ln_finalize_kernel(const float2* __restrict__ psum,
                                                          float2* __restrict__ st)
{
    int t = blockIdx.x * 256 + threadIdx.x;
    if (t >= TOK) return;
    const float2* p = psum + (size_t)t * NHEAD;
    float s = 0.f, q = 0.f;
#pragma unroll
    for (int hh = 0; hh < NHEAD; hh++) {
        float2 v = p[hh];
        s += v.x; q += v.y;
    }
    float mn = s * (1.0f / DMODEL);
    float vr = q * (1.0f / DMODEL) - mn * mn;
    st[t] = make_float2(mn, rsqrtf(vr + 1e-6f));
}

// ---------------- launcher -----------------------------------------------
extern "C" void kernel_launch(void* const* d_in, const int* in_sizes, int n_in,
                              void* d_out, int out_size)
{
    const float* x     = (const float*)d_in[0];
    const float* W_qkv = (const float*)d_in[1];
    const float* qs    = (const float*)d_in[2];
    const float* qb    = (const float*)d_in[3];
    const float* ks    = (const float*)d_in[4];
    const float* kb    = (const float*)d_in[5];
    const float* os    = (const float*)d_in[6];
    const float* ob    = (const float*)d_in[7];
    const float* W_out = (const float*)d_in[8];
    const float* b_out = (const float*)d_in[9];
    float* out = (float*)d_out;

    float *qkv_ptr, *attn_ptr;
    float2 *stat_ptr, *psum_ptr;
    cudaGetSymbolAddress((void**)&qkv_ptr, g_qkv);
    cudaGetSymbolAddress((void**)&attn_ptr, g_attn);
    cudaGetSymbolAddress((void**)&stat_ptr, g_stat);
    cudaGetSymbolAddress((void**)&psum_ptr, g_psum);

    // 1. QKV projection + fused per-head QK LayerNorm (+0.125 q scale)
    gemm_fused_kernel<1><<<dim3(TD / 64, TOK / 128), 256>>>(
        x, W_qkv, nullptr, qkv_ptr, TOK, TD, DMODEL,
        qs, qb, ks, kb, nullptr, nullptr, nullptr);

    // 2. attention (flash v2 frozen core + LN-partials epilogue)
    flash_mma_kernel<<<dim3(SEQ / 128, NBATCH * NHEAD), 256>>>(qkv_ptr, attn_ptr, psum_ptr);

    // 3. finalize LN stats from per-head partials (no 12.6MB re-read)
    ln_finalize_kernel<<<(TOK + 255) / 256, 256>>>(psum_ptr, stat_ptr);

    // 4. final projection with fused LN on A + bias
    gemm_fused_kernel<2><<<dim3(DMODEL / 64, TOK / 128), 256>>>(
        attn_ptr, W_out, b_out, out, TOK, DMODEL, DMODEL,
        nullptr, nullptr, nullptr, nullptr, stat_ptr, os, ob);
}

// round 16
// speedup vs baseline: 1.1790x; 1.0008x over previous
#include <cuda_runtime.h>
#include <cuda_bf16.h>
#include <stdint.h>
#include <math.h>

#define TOK   4096      // B*P
#define DMODEL 768
#define TD    2304      // 3*D
#define NHEAD 12
#define HD    64
#define SEQ   2048
#define NBATCH 2

// ---------------- scratch (no allocations allowed) ----------------
__device__ float  g_qkv[TOK * TD];      // [token, 3*D]
__device__ float  g_attn[TOK * DMODEL]; // attention output, pre-LN
__device__ float2 g_stat[TOK];          // (mean, rstd) of attention output rows

__device__ __forceinline__ void mma_bf16(float c[4], const uint32_t a[4], const uint32_t b[2])
{
    asm volatile(
        "mma.sync.aligned.m16n8k16.row.col.f32.bf16.bf16.f32 "
        "{%0,%1,%2,%3}, {%4,%5,%6,%7}, {%8,%9}, {%0,%1,%2,%3};"
        : "+f"(c[0]), "+f"(c[1]), "+f"(c[2]), "+f"(c[3])
        : "r"(a[0]), "r"(a[1]), "r"(a[2]), "r"(a[3]), "r"(b[0]), "r"(b[1]));
}

__device__ __forceinline__ void split_pack(float x0, float x1, uint32_t& hi, uint32_t& lo)
{
    __nv_bfloat16 h0 = __float2bfloat16(x0);
    __nv_bfloat16 h1 = __float2bfloat16(x1);
    __nv_bfloat16 l0 = __float2bfloat16(x0 - __bfloat162float(h0));
    __nv_bfloat16 l1 = __float2bfloat16(x1 - __bfloat162float(h1));
    hi = ((uint32_t)__bfloat16_as_ushort(h1) << 16) | (uint32_t)__bfloat16_as_ushort(h0);
    lo = ((uint32_t)__bfloat16_as_ushort(l1) << 16) | (uint32_t)__bfloat16_as_ushort(l0);
}

// =========================================================================
// bf16x3 tensor-core GEMM — R12 structure with DEEP PREFETCH:
// registers hold tile t+1 (loaded during iter t-1); storeTile(t+1) therefore
// never stalls on L2 latency; regs are refilled with tile t+2 right after.
// 128x64 block, 256 threads, double-buffered smem, sandwich STS schedule.
//  MODE 1: QKV proj + fused per-head QK LayerNorm (+0.125 q). v plain.
//  MODE 2: out proj, A-load applies LN via precomputed stats, + bias.
// =========================================================================
#define SA 12
#define SB 24

template<int MODE>
__global__ void __launch_bounds__(256) gemm_fused_kernel(
    const float* __restrict__ A, const float* __restrict__ B,
    const float* __restrict__ bias, float* __restrict__ C,
    int M, int N, int K,
    const float* __restrict__ qs, const float* __restrict__ qb,
    const float* __restrict__ ks, const float* __restrict__ kb,
    const float2* __restrict__ lnstat,
    const float* __restrict__ os, const float* __restrict__ ob)
{
    __shared__ uint32_t Ah[2][128][SA];
    __shared__ uint32_t Al[2][128][SA];
    __shared__ __nv_bfloat16 Bh[2][64][SB];
    __shared__ __nv_bfloat16 Bl[2][64][SB];
    __shared__ float2 red[128][2];

    const int tid  = threadIdx.x;
    const int lane = tid & 31;
    const int wid  = tid >> 5;
    const int wm   = wid & 3;
    const int wn   = wid >> 2;
    const int m0   = wm * 32;
    const int n0   = wn * 32;
    const int lr   = lane >> 2;
    const int lc   = lane & 3;

    const int blockM = blockIdx.y * 128;
    const int blockN = blockIdx.x * 64;

    const int am0 = tid >> 2;
    const int ak4 = (tid & 3) * 4;
    const float* Aptr0 = A + (size_t)(blockM + am0) * K + ak4;
    const float* Aptr1 = A + (size_t)(blockM + am0 + 64) * K + ak4;
    const int bk  = tid >> 4;
    const int bn4 = (tid & 15) * 4;
    const float* Bptr = B + (size_t)bk * N + blockN + bn4;

    float2 st0 = make_float2(0.f, 1.f), st1 = st0;
    if (MODE == 2) {
        st0 = lnstat[blockM + am0];
        st1 = lnstat[blockM + am0 + 64];
    }

    float acc[2][4][4];
#pragma unroll
    for (int i = 0; i < 2; i++)
#pragma unroll
        for (int j = 0; j < 4; j++)
#pragma unroll
            for (int k = 0; k < 4; k++) acc[i][j][k] = 0.f;

    const int T = K / 16;

    float4 aReg0, aReg1, bReg;
    float4 osv = make_float4(1,1,1,1), obv = make_float4(0,0,0,0);

    auto loadTile = [&](int t) {
        aReg0 = *(const float4*)(Aptr0 + t * 16);
        aReg1 = *(const float4*)(Aptr1 + t * 16);
        bReg  = *(const float4*)(Bptr + (size_t)t * 16 * N);
        if (MODE == 2) {
            osv = *(const float4*)(os + t * 16 + ak4);
            obv = *(const float4*)(ob + t * 16 + ak4);
        }
    };

    auto storeTile = [&](int buf) {
        float4 a0 = aReg0, a1 = aReg1;
        if (MODE == 2) {
            a0.x = (a0.x - st0.x) * st0.y * osv.x + obv.x;
            a0.y = (a0.y - st0.x) * st0.y * osv.y + obv.y;
            a0.z = (a0.z - st0.x) * st0.y * osv.z + obv.z;
            a0.w = (a0.w - st0.x) * st0.y * osv.w + obv.w;
            a1.x = (a1.x - st1.x) * st1.y * osv.x + obv.x;
            a1.y = (a1.y - st1.x) * st1.y * osv.y + obv.y;
            a1.z = (a1.z - st1.x) * st1.y * osv.z + obv.z;
            a1.w = (a1.w - st1.x) * st1.y * osv.w + obv.w;
        }
        uint32_t h, l;
        split_pack(a0.x, a0.y, h, l);
        Ah[buf][am0][ak4 / 2] = h; Al[buf][am0][ak4 / 2] = l;
        split_pack(a0.z, a0.w, h, l);
        Ah[buf][am0][ak4 / 2 + 1] = h; Al[buf][am0][ak4 / 2 + 1] = l;
        split_pack(a1.x, a1.y, h, l);
        Ah[buf][am0 + 64][ak4 / 2] = h; Al[buf][am0 + 64][ak4 / 2] = l;
        split_pack(a1.z, a1.w, h, l);
        Ah[buf][am0 + 64][ak4 / 2 + 1] = h; Al[buf][am0 + 64][ak4 / 2 + 1] = l;

        const float bv[4] = { bReg.x, bReg.y, bReg.z, bReg.w };
#pragma unroll
        for (int j = 0; j < 4; j++) {
            __nv_bfloat16 bh = __float2bfloat16(bv[j]);
            __nv_bfloat16 bl = __float2bfloat16(bv[j] - __bfloat162float(bh));
            Bh[buf][bn4 + j][bk] = bh;
            Bl[buf][bn4 + j][bk] = bl;
        }
    };

    // prologue: tile0 -> smem buf0; tile1 -> registers (in flight over sync)
    loadTile(0);
    storeTile(0);
    if (T > 1) loadTile(1);
    __syncthreads();

    for (int t = 0; t < T; t++) {
        const int cur = t & 1;

        uint32_t aFh[2][4], aFl[2][4], bFh[4][2], bFl[4][2];
#pragma unroll
        for (int mt = 0; mt < 2; mt++) {
            int r = m0 + 16 * mt + lr;
            aFh[mt][0] = Ah[cur][r][lc];     aFh[mt][1] = Ah[cur][r + 8][lc];
            aFh[mt][2] = Ah[cur][r][lc + 4]; aFh[mt][3] = Ah[cur][r + 8][lc + 4];
            aFl[mt][0] = Al[cur][r][lc];     aFl[mt][1] = Al[cur][r + 8][lc];
            aFl[mt][2] = Al[cur][r][lc + 4]; aFl[mt][3] = Al[cur][r + 8][lc + 4];
        }
#pragma unroll
        for (int nt = 0; nt < 4; nt++) {
            int n = n0 + 8 * nt + lr;
            bFh[nt][0] = *(const uint32_t*)&Bh[cur][n][2 * lc];
            bFh[nt][1] = *(const uint32_t*)&Bh[cur][n][2 * lc + 8];
            bFl[nt][0] = *(const uint32_t*)&Bl[cur][n][2 * lc];
            bFl[nt][1] = *(const uint32_t*)&Bl[cur][n][2 * lc + 8];
        }

        // ---- first half: mt=0 mmas ----
#pragma unroll
        for (int nt = 0; nt < 4; nt++) {
            mma_bf16(acc[0][nt], aFh[0], bFh[nt]);
            mma_bf16(acc[0][nt], aFh[0], bFl[nt]);
            mma_bf16(acc[0][nt], aFl[0], bFh[nt]);
        }

        // ---- store tile t+1 (regs arrived a full iteration ago) ----
        if (t + 1 < T) storeTile(cur ^ 1);
        // ---- refill regs with tile t+2 (lands during next iteration) ----
        if (t + 2 < T) loadTile(t + 2);

        // ---- second half: mt=1 mmas ----
#pragma unroll
        for (int nt = 0; nt < 4; nt++) {
            mma_bf16(acc[1][nt], aFh[1], bFh[nt]);
            mma_bf16(acc[1][nt], aFh[1], bFl[nt]);
            mma_bf16(acc[1][nt], aFl[1], bFh[nt]);
        }

        __syncthreads();
    }

    // ------------------ epilogue ------------------
    if (MODE == 1) {
        const int region = blockN / DMODEL;   // 0=q, 1=k, 2=v
        if (region < 2) {
            float mean[2][2], rstd[2][2];
#pragma unroll
            for (int mt = 0; mt < 2; mt++)
#pragma unroll
                for (int hf = 0; hf < 2; hf++) {
                    float s = 0.f, q = 0.f;
#pragma unroll
                    for (int nt = 0; nt < 4; nt++) {
                        float v0 = acc[mt][nt][2 * hf], v1 = acc[mt][nt][2 * hf + 1];
                        s += v0 + v1;
                        q += v0 * v0 + v1 * v1;
                    }
                    s += __shfl_xor_sync(0xffffffff, s, 1);
                    s += __shfl_xor_sync(0xffffffff, s, 2);
                    q += __shfl_xor_sync(0xffffffff, q, 1);
                    q += __shfl_xor_sync(0xffffffff, q, 2);
                    if (lc == 0)
                        red[m0 + 16 * mt + 8 * hf + lr][wn] = make_float2(s, q);
                }
            __syncthreads();
#pragma unroll
            for (int mt = 0; mt < 2; mt++)
#pragma unroll
                for (int hf = 0; hf < 2; hf++) {
                    float2 r0 = red[m0 + 16 * mt + 8 * hf + lr][0];
                    float2 r1 = red[m0 + 16 * mt + 8 * hf + lr][1];
                    float s = r0.x + r1.x, q = r0.y + r1.y;
                    float mn = s * (1.0f / 64.0f);
                    float vr = q * (1.0f / 64.0f) - mn * mn;
                    mean[mt][hf] = mn;
                    rstd[mt][hf] = rsqrtf(vr + 1e-6f);
                }

            const float* sc = region ? ks : qs;
            const float* bi = region ? kb : qb;
            const float mul = region ? 1.0f : 0.125f;

#pragma unroll
            for (int mt = 0; mt < 2; mt++) {
#pragma unroll
                for (int nt = 0; nt < 4; nt++) {
                    int c = n0 + 8 * nt + 2 * lc;
                    float s0 = sc[c] * mul, s1 = sc[c + 1] * mul;
                    float b0 = bi[c] * mul, b1 = bi[c + 1] * mul;
                    int row = blockM + m0 + 16 * mt + lr;
                    int col = blockN + c;
                    float2 v0 = { (acc[mt][nt][0] - mean[mt][0]) * rstd[mt][0] * s0 + b0,
                                  (acc[mt][nt][1] - mean[mt][0]) * rstd[mt][0] * s1 + b1 };
                    float2 v1 = { (acc[mt][nt][2] - mean[mt][1]) * rstd[mt][1] * s0 + b0,
                                  (acc[mt][nt][3] - mean[mt][1]) * rstd[mt][1] * s1 + b1 };
                    *(float2*)(C + (size_t)row * N + col)       = v0;
                    *(float2*)(C + (size_t)(row + 8) * N + col) = v1;
                }
            }
            return;
        }
#pragma unroll
        for (int mt = 0; mt < 2; mt++) {
#pragma unroll
            for (int nt = 0; nt < 4; nt++) {
                int row = blockM + m0 + 16 * mt + lr;
                int col = blockN + n0 + 8 * nt + 2 * lc;
                float2 v0 = { acc[mt][nt][0], acc[mt][nt][1] };
                float2 v1 = { acc[mt][nt][2], acc[mt][nt][3] };
                *(float2*)(C + (size_t)row * N + col)       = v0;
                *(float2*)(C + (size_t)(row + 8) * N + col) = v1;
            }
        }
        return;
    }

#pragma unroll
    for (int mt = 0; mt < 2; mt++) {
#pragma unroll
        for (int nt = 0; nt < 4; nt++) {
            int row = blockM + m0 + 16 * mt + lr;
            int col = blockN + n0 + 8 * nt + 2 * lc;
            float b0 = bias[col], b1 = bias[col + 1];
            float2 v0 = { acc[mt][nt][0] + b0, acc[mt][nt][1] + b1 };
            float2 v1 = { acc[mt][nt][2] + b0, acc[mt][nt][3] + b1 };
            *(float2*)(C + (size_t)row * N + col)       = v0;
            *(float2*)(C + (size_t)(row + 8) * N + col) = v1;
        }
    }
}

// =========================================================================
// Tensor-core flash attention (bf16x3) — the proven v2, verbatim. FROZEN.
// =========================================================================
#define KS 36

__global__ void __launch_bounds__(256) flash_mma_kernel(const float* __restrict__ qkv,
                                                        float* __restrict__ out)
{
    __shared__ uint32_t Kh[64][KS];
    __shared__ uint32_t Kl[64][KS];
    __shared__ uint32_t Vh[64][KS];   // transposed: [d][keypair], col swizzled
    __shared__ uint32_t Vl[64][KS];

    const int bh = blockIdx.y;
    const int b = bh / NHEAD, h = bh % NHEAD;
    const int q0 = blockIdx.x * 128;
    const int tid = threadIdx.x;
    const int lane = tid & 31;
    const int wid = tid >> 5;
    const int lr = lane >> 2;
    const int lc = lane & 3;

    uint32_t qh[4][4], ql[4][4];
    {
        const float* qb_ = qkv + (size_t)(b * SEQ + q0 + wid * 16) * TD + h * HD;
#pragma unroll
        for (int kt = 0; kt < 4; kt++) {
            int d = kt * 16 + 2 * lc;
            split_pack(qb_[(size_t)lr * TD + d],       qb_[(size_t)lr * TD + d + 1],       qh[kt][0], ql[kt][0]);
            split_pack(qb_[(size_t)(lr + 8) * TD + d], qb_[(size_t)(lr + 8) * TD + d + 1], qh[kt][1], ql[kt][1]);
            split_pack(qb_[(size_t)lr * TD + d + 8],       qb_[(size_t)lr * TD + d + 9],       qh[kt][2], ql[kt][2]);
            split_pack(qb_[(size_t)(lr + 8) * TD + d + 8], qb_[(size_t)(lr + 8) * TD + d + 9], qh[kt][3], ql[kt][3]);
        }
    }

    float o[8][4];
#pragma unroll
    for (int i = 0; i < 8; i++)
#pragma unroll
        for (int j = 0; j < 4; j++) o[i][j] = 0.f;
    float m0 = -INFINITY, m1 = -INFINITY, l0 = 0.f, l1 = 0.f;

    for (int jt = 0; jt < SEQ / 64; jt++) {
        __syncthreads();
        const float* kptr = qkv + (size_t)(b * SEQ + jt * 64) * TD + DMODEL + h * HD;
        const float* vptr = kptr + DMODEL;

#pragma unroll
        for (int i = 0; i < 8; i++) {
            int item = tid + i * 256;
            int key = item >> 5, dp = item & 31;
            float2 v = *(const float2*)(kptr + (size_t)key * TD + 2 * dp);
            uint32_t hh, ll;
            split_pack(v.x, v.y, hh, ll);
            Kh[key][dp] = hh; Kl[key][dp] = ll;
        }

#pragma unroll
        for (int r = 0; r < 4; r++) {
            int j = wid + 8 * r;
            const float* v0p = vptr + (size_t)(2 * j) * TD + 2 * lane;
            float2 a = *(const float2*)v0p;
            float2 c = *(const float2*)(v0p + TD);
            int d0 = 2 * lane;
            int jc = (j & ~7) | ((j & 7) ^ (lane & 7));
            uint32_t hh, ll;
            split_pack(a.x, c.x, hh, ll);
            Vh[d0][jc] = hh; Vl[d0][jc] = ll;
            split_pack(a.y, c.y, hh, ll);
            Vh[d0 + 1][jc] = hh; Vl[d0 + 1][jc] = ll;
        }
        __syncthreads();

        float s[8][4];
#pragma unroll
        for (int nt = 0; nt < 8; nt++) {
            float c[4] = {0.f, 0.f, 0.f, 0.f};
#pragma unroll
            for (int kt = 0; kt < 4; kt++) {
                int krow = 8 * nt + lr;
                uint32_t bhf[2] = { Kh[krow][8 * kt + lc], Kh[krow][8 * kt + 4 + lc] };
                uint32_t blf[2] = { Kl[krow][8 * kt + lc], Kl[krow][8 * kt + 4 + lc] };
                mma_bf16(c, qh[kt], bhf);
                mma_bf16(c, qh[kt], blf);
                mma_bf16(c, ql[kt], bhf);
            }
            s[nt][0] = c[0]; s[nt][1] = c[1]; s[nt][2] = c[2]; s[nt][3] = c[3];
        }

        float rmax0 = -INFINITY, rmax1 = -INFINITY;
#pragma unroll
        for (int nt = 0; nt < 8; nt++) {
            rmax0 = fmaxf(rmax0, fmaxf(s[nt][0], s[nt][1]));
            rmax1 = fmaxf(rmax1, fmaxf(s[nt][2], s[nt][3]));
        }
        rmax0 = fmaxf(rmax0, __shfl_xor_sync(0xffffffff, rmax0, 1));
        rmax0 = fmaxf(rmax0, __shfl_xor_sync(0xffffffff, rmax0, 2));
        rmax1 = fmaxf(rmax1, __shfl_xor_sync(0xffffffff, rmax1, 1));
        rmax1 = fmaxf(rmax1, __shfl_xor_sync(0xffffffff, rmax1, 2));

        float mn0 = fmaxf(m0, rmax0), mn1 = fmaxf(m1, rmax1);
        float sc0 = __expf(m0 - mn0), sc1 = __expf(m1 - mn1);
        l0 *= sc0; l1 *= sc1;
        m0 = mn0; m1 = mn1;
#pragma unroll
        for (int nt = 0; nt < 8; nt++) {
            o[nt][0] *= sc0; o[nt][1] *= sc0;
            o[nt][2] *= sc1; o[nt][3] *= sc1;
        }

        uint32_t Ph0[8], Ph1[8], Pl0[8], Pl1[8];
        float ps0 = 0.f, ps1 = 0.f;
#pragma unroll
        for (int nt = 0; nt < 8; nt++) {
            float p0 = __expf(s[nt][0] - mn0);
            float p1 = __expf(s[nt][1] - mn0);
            float p2 = __expf(s[nt][2] - mn1);
            float p3 = __expf(s[nt][3] - mn1);
            ps0 += p0 + p1; ps1 += p2 + p3;
            split_pack(p0, p1, Ph0[nt], Pl0[nt]);
            split_pack(p2, p3, Ph1[nt], Pl1[nt]);
        }
        ps0 += __shfl_xor_sync(0xffffffff, ps0, 1);
        ps0 += __shfl_xor_sync(0xffffffff, ps0, 2);
        ps1 += __shfl_xor_sync(0xffffffff, ps1, 1);
        ps1 += __shfl_xor_sync(0xffffffff, ps1, 2);
        l0 += ps0; l1 += ps1;

#pragma unroll
        for (int nt = 0; nt < 8; nt++) {
            int drow = 8 * nt + lr;
            int xsw = (drow >> 1) & 7;
#pragma unroll
            for (int kt = 0; kt < 4; kt++) {
                uint32_t ah[4] = { Ph0[2 * kt], Ph1[2 * kt], Ph0[2 * kt + 1], Ph1[2 * kt + 1] };
                uint32_t al[4] = { Pl0[2 * kt], Pl1[2 * kt], Pl0[2 * kt + 1], Pl1[2 * kt + 1] };
                int jc0 = 8 * kt + (lc ^ xsw);
                int jc1 = 8 * kt + ((lc + 4) ^ xsw);
                uint32_t bhf[2] = { Vh[drow][jc0], Vh[drow][jc1] };
                uint32_t blf[2] = { Vl[drow][jc0], Vl[drow][jc1] };
                mma_bf16(o[nt], ah, bhf);
                mma_bf16(o[nt], ah, blf);
                mma_bf16(o[nt], al, bhf);
            }
        }
    }

    const float inv0 = 1.0f / l0, inv1 = 1.0f / l1;
    const int row0 = b * SEQ + q0 + wid * 16 + lr;
#pragma unroll
    for (int nt = 0; nt < 8; nt++) {
        int col = h * HD + 8 * nt + 2 * lc;
        float2 v0 = { o[nt][0] * inv0, o[nt][1] * inv0 };
        float2 v1 = { o[nt][2] * inv1, o[nt][3] * inv1 };
        *(float2*)(out + (size_t)row0 * DMODEL + col)       = v0;
        *(float2*)(out + (size_t)(row0 + 8) * DMODEL + col) = v1;
    }
}

// ---------------- LayerNorm stats (mean, rstd) per token row --------------
__global__ void __launch_bounds__(256) ln_stats_kernel(const float* __restrict__ in,
                                                       float2* __restrict__ st)
{
    const int warp = (blockIdx.x * blockDim.x + threadIdx.x) >> 5;
    const int lane = threadIdx.x & 31;
    if (warp >= TOK) return;

    const float4* row = (const float4*)(in + (size_t)warp * DMODEL);
    float s = 0.f, q = 0.f;
#pragma unroll
    for (int i = 0; i < 6; i++) {
        float4 v = row[lane + 32 * i];
        s += v.x + v.y + v.z + v.w;
        q += v.x * v.x + v.y * v.y + v.z * v.z + v.w * v.w;
    }
#pragma unroll
    for (int off = 16; off > 0; off >>= 1) {
        s += __shfl_xor_sync(0xffffffff, s, off);
        q += __shfl_xor_sync(0xffffffff, q, off);
    }
    if (lane == 0) {
        float mn = s * (1.0f / DMODEL);
        float vr = q * (1.0f / DMODEL) - mn * mn;
        st[warp] = make_float2(mn, rsqrtf(vr + 1e-6f));
    }
}

// ---------------- launcher -----------------------------------------------
extern "C" void kernel_launch(void* const* d_in, const int* in_sizes, int n_in,
                              void* d_out, int out_size)
{
    const float* x     = (const float*)d_in[0];
    const float* W_qkv = (const float*)d_in[1];
    const float* qs    = (const float*)d_in[2];
    const float* qb    = (const float*)d_in[3];
    const float* ks    = (const float*)d_in[4];
    const float* kb    = (const float*)d_in[5];
    const float* os    = (const float*)d_in[6];
    const float* ob    = (const float*)d_in[7];
    const float* W_out = (const float*)d_in[8];
    const float* b_out = (const float*)d_in[9];
    float* out = (float*)d_out;

    float *qkv_ptr, *attn_ptr;
    float2* stat_ptr;
    cudaGetSymbolAddress((void**)&qkv_ptr, g_qkv);
    cudaGetSymbolAddress((void**)&attn_ptr, g_attn);
    cudaGetSymbolAddress((void**)&stat_ptr, g_stat);

    // 1. QKV projection + fused per-head QK LayerNorm (+0.125 q scale)
    gemm_fused_kernel<1><<<dim3(TD / 64, TOK / 128), 256>>>(
        x, W_qkv, nullptr, qkv_ptr, TOK, TD, DMODEL,
        qs, qb, ks, kb, nullptr, nullptr, nullptr);

    // 2. attention (tensor-core flash v2 — frozen)
    flash_mma_kernel<<<dim3(SEQ / 128, NBATCH * NHEAD), 256>>>(qkv_ptr, attn_ptr);

    // 3. output LayerNorm stats
    ln_stats_kernel<<<TOK / 8, 256>>>(attn_ptr, stat_ptr);

    // 4. final projection with fused LN on A + bias
    gemm_fused_kernel<2><<<dim3(DMODEL / 64, TOK / 128), 256>>>(
        attn_ptr, W_out, b_out, out, TOK, DMODEL, DMODEL,
        nullptr, nullptr, nullptr, nullptr, stat_ptr, os, ob);
}

// round 17
// speedup vs baseline: 1.2101x; 1.0264x over previous
#include <cuda_runtime.h>
#include <cuda_bf16.h>
#include <stdint.h>
#include <math.h>

#define TOK   4096      // B*P
#define DMODEL 768
#define TD    2304      // 3*D
#define NHEAD 12
#define HD    64
#define SEQ   2048
#define NBATCH 2

// ---------------- scratch (no allocations allowed) ----------------
__device__ float  g_qkv[TOK * TD];      // [token, 3*D]
__device__ float  g_attn[TOK * DMODEL]; // attention output, pre-LN
__device__ float2 g_stat[TOK];          // (mean, rstd) of attention output rows

__device__ __forceinline__ void mma_bf16(float c[4], const uint32_t a[4], const uint32_t b[2])
{
    asm volatile(
        "mma.sync.aligned.m16n8k16.row.col.f32.bf16.bf16.f32 "
        "{%0,%1,%2,%3}, {%4,%5,%6,%7}, {%8,%9}, {%0,%1,%2,%3};"
        : "+f"(c[0]), "+f"(c[1]), "+f"(c[2]), "+f"(c[3])
        : "r"(a[0]), "r"(a[1]), "r"(a[2]), "r"(a[3]), "r"(b[0]), "r"(b[1]));
}

__device__ __forceinline__ void split_pack(float x0, float x1, uint32_t& hi, uint32_t& lo)
{
    __nv_bfloat16 h0 = __float2bfloat16(x0);
    __nv_bfloat16 h1 = __float2bfloat16(x1);
    __nv_bfloat16 l0 = __float2bfloat16(x0 - __bfloat162float(h0));
    __nv_bfloat16 l1 = __float2bfloat16(x1 - __bfloat162float(h1));
    hi = ((uint32_t)__bfloat16_as_ushort(h1) << 16) | (uint32_t)__bfloat16_as_ushort(h0);
    lo = ((uint32_t)__bfloat16_as_ushort(l1) << 16) | (uint32_t)__bfloat16_as_ushort(l0);
}

// =========================================================================
// bf16x3 tensor-core GEMM — BK=32 chunked: one __syncthreads per 32-K tile
// (half the barrier count of the proven R12 kernel), same mma order,
// same prefetch register footprint (chunks streamed sequentially).
// 128x64 block, 256 threads, double-buffered dynamic smem.
//  MODE 1: QKV proj + fused per-head QK LayerNorm (+0.125 q). v plain.
//  MODE 2: out proj, A-load applies LN via precomputed stats, + bias.
// =========================================================================
#define SAW 20   // uint32 stride per A row (16 used)
#define SBW 40   // bf16 stride per B row (32 used)

struct GemmSmem {
    uint32_t Ah[2][128][SAW];
    uint32_t Al[2][128][SAW];
    __nv_bfloat16 Bh[2][64][SBW];
    __nv_bfloat16 Bl[2][64][SBW];
    float2 red[128][2];
};
#define GEMM_SMEM_BYTES sizeof(GemmSmem)   // 63488

template<int MODE>
__global__ void __launch_bounds__(256) gemm_fused_kernel(
    const float* __restrict__ A, const float* __restrict__ B,
    const float* __restrict__ bias, float* __restrict__ C,
    int M, int N, int K,
    const float* __restrict__ qs, const float* __restrict__ qb,
    const float* __restrict__ ks, const float* __restrict__ kb,
    const float2* __restrict__ lnstat,
    const float* __restrict__ os, const float* __restrict__ ob)
{
    extern __shared__ char raw_smem[];
    GemmSmem& sm = *reinterpret_cast<GemmSmem*>(raw_smem);

    const int tid  = threadIdx.x;
    const int lane = tid & 31;
    const int wid  = tid >> 5;
    const int wm   = wid & 3;
    const int wn   = wid >> 2;
    const int m0   = wm * 32;
    const int n0   = wn * 32;
    const int lr   = lane >> 2;
    const int lc   = lane & 3;

    const int blockM = blockIdx.y * 128;
    const int blockN = blockIdx.x * 64;

    const int am0 = tid >> 2;
    const int ak4 = (tid & 3) * 4;
    const float* Aptr0 = A + (size_t)(blockM + am0) * K + ak4;
    const float* Aptr1 = A + (size_t)(blockM + am0 + 64) * K + ak4;
    const int bk  = tid >> 4;
    const int bn4 = (tid & 15) * 4;
    const float* Bptr = B + (size_t)bk * N + blockN + bn4;

    float2 st0 = make_float2(0.f, 1.f), st1 = st0;
    if (MODE == 2) {
        st0 = lnstat[blockM + am0];
        st1 = lnstat[blockM + am0 + 64];
    }

    float acc[2][4][4];
#pragma unroll
    for (int i = 0; i < 2; i++)
#pragma unroll
        for (int j = 0; j < 4; j++)
#pragma unroll
            for (int k = 0; k < 4; k++) acc[i][j][k] = 0.f;

    const int T = K / 32;     // 32-K tiles

    float4 aReg0, aReg1, bReg;
    float4 osv = make_float4(1,1,1,1), obv = make_float4(0,0,0,0);

    // load one 16-K chunk (kk in {0,1}) of tile t into registers
    auto loadChunk = [&](int t, int kk) {
        int k0 = t * 32 + kk * 16;
        aReg0 = *(const float4*)(Aptr0 + k0);
        aReg1 = *(const float4*)(Aptr1 + k0);
        bReg  = *(const float4*)(Bptr + (size_t)k0 * N);
        if (MODE == 2) {
            osv = *(const float4*)(os + k0 + ak4);
            obv = *(const float4*)(ob + k0 + ak4);
        }
    };

    auto storeChunk = [&](int buf, int kk) {
        float4 a0 = aReg0, a1 = aReg1;
        if (MODE == 2) {
            a0.x = (a0.x - st0.x) * st0.y * osv.x + obv.x;
            a0.y = (a0.y - st0.x) * st0.y * osv.y + obv.y;
            a0.z = (a0.z - st0.x) * st0.y * osv.z + obv.z;
            a0.w = (a0.w - st0.x) * st0.y * osv.w + obv.w;
            a1.x = (a1.x - st1.x) * st1.y * osv.x + obv.x;
            a1.y = (a1.y - st1.x) * st1.y * osv.y + obv.y;
            a1.z = (a1.z - st1.x) * st1.y * osv.z + obv.z;
            a1.w = (a1.w - st1.x) * st1.y * osv.w + obv.w;
        }
        const int ac = kk * 8 + ak4 / 2;
        uint32_t h, l;
        split_pack(a0.x, a0.y, h, l);
        sm.Ah[buf][am0][ac] = h; sm.Al[buf][am0][ac] = l;
        split_pack(a0.z, a0.w, h, l);
        sm.Ah[buf][am0][ac + 1] = h; sm.Al[buf][am0][ac + 1] = l;
        split_pack(a1.x, a1.y, h, l);
        sm.Ah[buf][am0 + 64][ac] = h; sm.Al[buf][am0 + 64][ac] = l;
        split_pack(a1.z, a1.w, h, l);
        sm.Ah[buf][am0 + 64][ac + 1] = h; sm.Al[buf][am0 + 64][ac + 1] = l;

        const int bc = kk * 16 + bk;
        const float bv[4] = { bReg.x, bReg.y, bReg.z, bReg.w };
#pragma unroll
        for (int j = 0; j < 4; j++) {
            __nv_bfloat16 bh = __float2bfloat16(bv[j]);
            __nv_bfloat16 bl = __float2bfloat16(bv[j] - __bfloat162float(bh));
            sm.Bh[buf][bn4 + j][bc] = bh;
            sm.Bl[buf][bn4 + j][bc] = bl;
        }
    };

    // prologue: tile 0 fully into buffer 0
    loadChunk(0, 0); storeChunk(0, 0);
    loadChunk(0, 1); storeChunk(0, 1);
    __syncthreads();

    uint32_t aFh[2][4], aFl[2][4], bFh[4][2], bFl[4][2];

    auto loadFrags = [&](int cur, int kk) {
        const int ab = kk * 8;
        const int bb = kk * 16;
#pragma unroll
        for (int mt = 0; mt < 2; mt++) {
            int r = m0 + 16 * mt + lr;
            aFh[mt][0] = sm.Ah[cur][r][ab + lc];     aFh[mt][1] = sm.Ah[cur][r + 8][ab + lc];
            aFh[mt][2] = sm.Ah[cur][r][ab + lc + 4]; aFh[mt][3] = sm.Ah[cur][r + 8][ab + lc + 4];
            aFl[mt][0] = sm.Al[cur][r][ab + lc];     aFl[mt][1] = sm.Al[cur][r + 8][ab + lc];
            aFl[mt][2] = sm.Al[cur][r][ab + lc + 4]; aFl[mt][3] = sm.Al[cur][r + 8][ab + lc + 4];
        }
#pragma unroll
        for (int nt = 0; nt < 4; nt++) {
            int n = n0 + 8 * nt + lr;
            bFh[nt][0] = *(const uint32_t*)&sm.Bh[cur][n][bb + 2 * lc];
            bFh[nt][1] = *(const uint32_t*)&sm.Bh[cur][n][bb + 2 * lc + 8];
            bFl[nt][0] = *(const uint32_t*)&sm.Bl[cur][n][bb + 2 * lc];
            bFl[nt][1] = *(const uint32_t*)&sm.Bl[cur][n][bb + 2 * lc + 8];
        }
    };

    auto mmaHalf = [&](int mt) {
#pragma unroll
        for (int nt = 0; nt < 4; nt++) {
            mma_bf16(acc[mt][nt], aFh[mt], bFh[nt]);
            mma_bf16(acc[mt][nt], aFh[mt], bFl[nt]);
            mma_bf16(acc[mt][nt], aFl[mt], bFh[nt]);
        }
    };

    for (int t = 0; t < T; t++) {
        const int cur = t & 1;
        const bool more = (t + 1 < T);

        if (more) loadChunk(t + 1, 0);          // LDG chunk0 of next tile
        loadFrags(cur, 0);
        mmaHalf(0);                             // 12 mmas cover chunk0 LDG
        if (more) { storeChunk(cur ^ 1, 0); loadChunk(t + 1, 1); }
        mmaHalf(1);

        loadFrags(cur, 1);
        mmaHalf(0);                             // 12+12 mmas cover chunk1 LDG
        if (more) storeChunk(cur ^ 1, 1);
        mmaHalf(1);                             // STS drains over these mmas

        __syncthreads();                        // ONE barrier per 32-K
    }

    // ------------------ epilogue ------------------
    if (MODE == 1) {
        const int region = blockN / DMODEL;   // 0=q, 1=k, 2=v
        if (region < 2) {
            float mean[2][2], rstd[2][2];
#pragma unroll
            for (int mt = 0; mt < 2; mt++)
#pragma unroll
                for (int hf = 0; hf < 2; hf++) {
                    float s = 0.f, q = 0.f;
#pragma unroll
                    for (int nt = 0; nt < 4; nt++) {
                        float v0 = acc[mt][nt][2 * hf], v1 = acc[mt][nt][2 * hf + 1];
                        s += v0 + v1;
                        q += v0 * v0 + v1 * v1;
                    }
                    s += __shfl_xor_sync(0xffffffff, s, 1);
                    s += __shfl_xor_sync(0xffffffff, s, 2);
                    q += __shfl_xor_sync(0xffffffff, q, 1);
                    q += __shfl_xor_sync(0xffffffff, q, 2);
                    if (lc == 0)
                        sm.red[m0 + 16 * mt + 8 * hf + lr][wn] = make_float2(s, q);
                }
            __syncthreads();
#pragma unroll
            for (int mt = 0; mt < 2; mt++)
#pragma unroll
                for (int hf = 0; hf < 2; hf++) {
                    float2 r0 = sm.red[m0 + 16 * mt + 8 * hf + lr][0];
                    float2 r1 = sm.red[m0 + 16 * mt + 8 * hf + lr][1];
                    float s = r0.x + r1.x, q = r0.y + r1.y;
                    float mn = s * (1.0f / 64.0f);
                    float vr = q * (1.0f / 64.0f) - mn * mn;
                    mean[mt][hf] = mn;
                    rstd[mt][hf] = rsqrtf(vr + 1e-6f);
                }

            const float* sc = region ? ks : qs;
            const float* bi = region ? kb : qb;
            const float mul = region ? 1.0f : 0.125f;

#pragma unroll
            for (int mt = 0; mt < 2; mt++) {
#pragma unroll
                for (int nt = 0; nt < 4; nt++) {
                    int c = n0 + 8 * nt + 2 * lc;
                    float s0 = sc[c] * mul, s1 = sc[c + 1] * mul;
                    float b0 = bi[c] * mul, b1 = bi[c + 1] * mul;
                    int row = blockM + m0 + 16 * mt + lr;
                    int col = blockN + c;
                    float2 v0 = { (acc[mt][nt][0] - mean[mt][0]) * rstd[mt][0] * s0 + b0,
                                  (acc[mt][nt][1] - mean[mt][0]) * rstd[mt][0] * s1 + b1 };
                    float2 v1 = { (acc[mt][nt][2] - mean[mt][1]) * rstd[mt][1] * s0 + b0,
                                  (acc[mt][nt][3] - mean[mt][1]) * rstd[mt][1] * s1 + b1 };
                    *(float2*)(C + (size_t)row * N + col)       = v0;
                    *(float2*)(C + (size_t)(row + 8) * N + col) = v1;
                }
            }
            return;
        }
#pragma unroll
        for (int mt = 0; mt < 2; mt++) {
#pragma unroll
            for (int nt = 0; nt < 4; nt++) {
                int row = blockM + m0 + 16 * mt + lr;
                int col = blockN + n0 + 8 * nt + 2 * lc;
                float2 v0 = { acc[mt][nt][0], acc[mt][nt][1] };
                float2 v1 = { acc[mt][nt][2], acc[mt][nt][3] };
                *(float2*)(C + (size_t)row * N + col)       = v0;
                *(float2*)(C + (size_t)(row + 8) * N + col) = v1;
            }
        }
        return;
    }

#pragma unroll
    for (int mt = 0; mt < 2; mt++) {
#pragma unroll
        for (int nt = 0; nt < 4; nt++) {
            int row = blockM + m0 + 16 * mt + lr;
            int col = blockN + n0 + 8 * nt + 2 * lc;
            float b0 = bias[col], b1 = bias[col + 1];
            float2 v0 = { acc[mt][nt][0] + b0, acc[mt][nt][1] + b1 };
            float2 v1 = { acc[mt][nt][2] + b0, acc[mt][nt][3] + b1 };
            *(float2*)(C + (size_t)row * N + col)       = v0;
            *(float2*)(C + (size_t)(row + 8) * N + col) = v1;
        }
    }
}

// =========================================================================
// Tensor-core flash attention (bf16x3) — the proven v2, verbatim. FROZEN.
// =========================================================================
#define KS 36

__global__ void __launch_bounds__(256) flash_mma_kernel(const float* __restrict__ qkv,
                                                        float* __restrict__ out)
{
    __shared__ uint32_t Kh[64][KS];
    __shared__ uint32_t Kl[64][KS];
    __shared__ uint32_t Vh[64][KS];   // transposed: [d][keypair], col swizzled
    __shared__ uint32_t Vl[64][KS];

    const int bh = blockIdx.y;
    const int b = bh / NHEAD, h = bh % NHEAD;
    const int q0 = blockIdx.x * 128;
    const int tid = threadIdx.x;
    const int lane = tid & 31;
    const int wid = tid >> 5;
    const int lr = lane >> 2;
    const int lc = lane & 3;

    uint32_t qh[4][4], ql[4][4];
    {
        const float* qb_ = qkv + (size_t)(b * SEQ + q0 + wid * 16) * TD + h * HD;
#pragma unroll
        for (int kt = 0; kt < 4; kt++) {
            int d = kt * 16 + 2 * lc;
            split_pack(qb_[(size_t)lr * TD + d],       qb_[(size_t)lr * TD + d + 1],       qh[kt][0], ql[kt][0]);
            split_pack(qb_[(size_t)(lr + 8) * TD + d], qb_[(size_t)(lr + 8) * TD + d + 1], qh[kt][1], ql[kt][1]);
            split_pack(qb_[(size_t)lr * TD + d + 8],       qb_[(size_t)lr * TD + d + 9],       qh[kt][2], ql[kt][2]);
            split_pack(qb_[(size_t)(lr + 8) * TD + d + 8], qb_[(size_t)(lr + 8) * TD + d + 9], qh[kt][3], ql[kt][3]);
        }
    }

    float o[8][4];
#pragma unroll
    for (int i = 0; i < 8; i++)
#pragma unroll
        for (int j = 0; j < 4; j++) o[i][j] = 0.f;
    float m0 = -INFINITY, m1 = -INFINITY, l0 = 0.f, l1 = 0.f;

    for (int jt = 0; jt < SEQ / 64; jt++) {
        __syncthreads();
        const float* kptr = qkv + (size_t)(b * SEQ + jt * 64) * TD + DMODEL + h * HD;
        const float* vptr = kptr + DMODEL;

#pragma unroll
        for (int i = 0; i < 8; i++) {
            int item = tid + i * 256;
            int key = item >> 5, dp = item & 31;
            float2 v = *(const float2*)(kptr + (size_t)key * TD + 2 * dp);
            uint32_t hh, ll;
            split_pack(v.x, v.y, hh, ll);
            Kh[key][dp] = hh; Kl[key][dp] = ll;
        }

#pragma unroll
        for (int r = 0; r < 4; r++) {
            int j = wid + 8 * r;
            const float* v0p = vptr + (size_t)(2 * j) * TD + 2 * lane;
            float2 a = *(const float2*)v0p;
            float2 c = *(const float2*)(v0p + TD);
            int d0 = 2 * lane;
            int jc = (j & ~7) | ((j & 7) ^ (lane & 7));
            uint32_t hh, ll;
            split_pack(a.x, c.x, hh, ll);
            Vh[d0][jc] = hh; Vl[d0][jc] = ll;
            split_pack(a.y, c.y, hh, ll);
            Vh[d0 + 1][jc] = hh; Vl[d0 + 1][jc] = ll;
        }
        __syncthreads();

        float s[8][4];
#pragma unroll
        for (int nt = 0; nt < 8; nt++) {
            float c[4] = {0.f, 0.f, 0.f, 0.f};
#pragma unroll
            for (int kt = 0; kt < 4; kt++) {
                int krow = 8 * nt + lr;
                uint32_t bhf[2] = { Kh[krow][8 * kt + lc], Kh[krow][8 * kt + 4 + lc] };
                uint32_t blf[2] = { Kl[krow][8 * kt + lc], Kl[krow][8 * kt + 4 + lc] };
                mma_bf16(c, qh[kt], bhf);
                mma_bf16(c, qh[kt], blf);
                mma_bf16(c, ql[kt], bhf);
            }
            s[nt][0] = c[0]; s[nt][1] = c[1]; s[nt][2] = c[2]; s[nt][3] = c[3];
        }

        float rmax0 = -INFINITY, rmax1 = -INFINITY;
#pragma unroll
        for (int nt = 0; nt < 8; nt++) {
            rmax0 = fmaxf(rmax0, fmaxf(s[nt][0], s[nt][1]));
            rmax1 = fmaxf(rmax1, fmaxf(s[nt][2], s[nt][3]));
        }
        rmax0 = fmaxf(rmax0, __shfl_xor_sync(0xffffffff, rmax0, 1));
        rmax0 = fmaxf(rmax0, __shfl_xor_sync(0xffffffff, rmax0, 2));
        rmax1 = fmaxf(rmax1, __shfl_xor_sync(0xffffffff, rmax1, 1));
        rmax1 = fmaxf(rmax1, __shfl_xor_sync(0xffffffff, rmax1, 2));

        float mn0 = fmaxf(m0, rmax0), mn1 = fmaxf(m1, rmax1);
        float sc0 = __expf(m0 - mn0), sc1 = __expf(m1 - mn1);
        l0 *= sc0; l1 *= sc1;
        m0 = mn0; m1 = mn1;
#pragma unroll
        for (int nt = 0; nt < 8; nt++) {
            o[nt][0] *= sc0; o[nt][1] *= sc0;
            o[nt][2] *= sc1; o[nt][3] *= sc1;
        }

        uint32_t Ph0[8], Ph1[8], Pl0[8], Pl1[8];
        float ps0 = 0.f, ps1 = 0.f;
#pragma unroll
        for (int nt = 0; nt < 8; nt++) {
            float p0 = __expf(s[nt][0] - mn0);
            float p1 = __expf(s[nt][1] - mn0);
            float p2 = __expf(s[nt][2] - mn1);
            float p3 = __expf(s[nt][3] - mn1);
            ps0 += p0 + p1; ps1 += p2 + p3;
            split_pack(p0, p1, Ph0[nt], Pl0[nt]);
            split_pack(p2, p3, Ph1[nt], Pl1[nt]);
        }
        ps0 += __shfl_xor_sync(0xffffffff, ps0, 1);
        ps0 += __shfl_xor_sync(0xffffffff, ps0, 2);
        ps1 += __shfl_xor_sync(0xffffffff, ps1, 1);
        ps1 += __shfl_xor_sync(0xffffffff, ps1, 2);
        l0 += ps0; l1 += ps1;

#pragma unroll
        for (int nt = 0; nt < 8; nt++) {
            int drow = 8 * nt + lr;
            int xsw = (drow >> 1) & 7;
#pragma unroll
            for (int kt = 0; kt < 4; kt++) {
                uint32_t ah[4] = { Ph0[2 * kt], Ph1[2 * kt], Ph0[2 * kt + 1], Ph1[2 * kt + 1] };
                uint32_t al[4] = { Pl0[2 * kt], Pl1[2 * kt], Pl0[2 * kt + 1], Pl1[2 * kt + 1] };
                int jc0 = 8 * kt + (lc ^ xsw);
                int jc1 = 8 * kt + ((lc + 4) ^ xsw);
                uint32_t bhf[2] = { Vh[drow][jc0], Vh[drow][jc1] };
                uint32_t blf[2] = { Vl[drow][jc0], Vl[drow][jc1] };
                mma_bf16(o[nt], ah, bhf);
                mma_bf16(o[nt], ah, blf);
                mma_bf16(o[nt], al, bhf);
            }
        }
    }

    const float inv0 = 1.0f / l0, inv1 = 1.0f / l1;
    const int row0 = b * SEQ + q0 + wid * 16 + lr;
#pragma unroll
    for (int nt = 0; nt < 8; nt++) {
        int col = h * HD + 8 * nt + 2 * lc;
        float2 v0 = { o[nt][0] * inv0, o[nt][1] * inv0 };
        float2 v1 = { o[nt][2] * inv1, o[nt][3] * inv1 };
        *(float2*)(out + (size_t)row0 * DMODEL + col)       = v0;
        *(float2*)(out + (size_t)(row0 + 8) * DMODEL + col) = v1;
    }
}

// ---------------- LayerNorm stats (mean, rstd) per token row --------------
__global__ void __launch_bounds__(256) ln_stats_kernel(const float* __restrict__ in,
                                                       float2* __restrict__ st)
{
    const int warp = (blockIdx.x * blockDim.x + threadIdx.x) >> 5;
    const int lane = threadIdx.x & 31;
    if (warp >= TOK) return;

    const float4* row = (const float4*)(in + (size_t)warp * DMODEL);
    float s = 0.f, q = 0.f;
#pragma unroll
    for (int i = 0; i < 6; i++) {
        float4 v = row[lane + 32 * i];
        s += v.x + v.y + v.z + v.w;
        q += v.x * v.x + v.y * v.y + v.z * v.z + v.w * v.w;
    }
#pragma unroll
    for (int off = 16; off > 0; off >>= 1) {
        s += __shfl_xor_sync(0xffffffff, s, off);
        q += __shfl_xor_sync(0xffffffff, q, off);
    }
    if (lane == 0) {
        float mn = s * (1.0f / DMODEL);
        float vr = q * (1.0f / DMODEL) - mn * mn;
        st[warp] = make_float2(mn, rsqrtf(vr + 1e-6f));
    }
}

// ---------------- launcher -----------------------------------------------
extern "C" void kernel_launch(void* const* d_in, const int* in_sizes, int n_in,
                              void* d_out, int out_size)
{
    const float* x     = (const float*)d_in[0];
    const float* W_qkv = (const float*)d_in[1];
    const float* qs    = (const float*)d_in[2];
    const float* qb    = (const float*)d_in[3];
    const float* ks    = (const float*)d_in[4];
    const float* kb    = (const float*)d_in[5];
    const float* os    = (const float*)d_in[6];
    const float* ob    = (const float*)d_in[7];
    const float* W_out = (const float*)d_in[8];
    const float* b_out = (const float*)d_in[9];
    float* out = (float*)d_out;

    float *qkv_ptr, *attn_ptr;
    float2* stat_ptr;
    cudaGetSymbolAddress((void**)&qkv_ptr, g_qkv);
    cudaGetSymbolAddress((void**)&attn_ptr, g_attn);
    cudaGetSymbolAddress((void**)&stat_ptr, g_stat);

    cudaFuncSetAttribute(gemm_fused_kernel<1>,
                         cudaFuncAttributeMaxDynamicSharedMemorySize, (int)GEMM_SMEM_BYTES);
    cudaFuncSetAttribute(gemm_fused_kernel<2>,
                         cudaFuncAttributeMaxDynamicSharedMemorySize, (int)GEMM_SMEM_BYTES);

    // 1. QKV projection + fused per-head QK LayerNorm (+0.125 q scale)
    gemm_fused_kernel<1><<<dim3(TD / 64, TOK / 128), 256, GEMM_SMEM_BYTES>>>(
        x, W_qkv, nullptr, qkv_ptr, TOK, TD, DMODEL,
        qs, qb, ks, kb, nullptr, nullptr, nullptr);

    // 2. attention (tensor-core flash v2 — frozen)
    flash_mma_kernel<<<dim3(SEQ / 128, NBATCH * NHEAD), 256>>>(qkv_ptr, attn_ptr);

    // 3. output LayerNorm stats
    ln_stats_kernel<<<TOK / 8, 256>>>(attn_ptr, stat_ptr);

    // 4. final projection with fused LN on A + bias
    gemm_fused_kernel<2><<<dim3(DMODEL / 64, TOK / 128), 256, GEMM_SMEM_BYTES>>>(
        attn_ptr, W_out, b_out, out, TOK, DMODEL, DMODEL,
        nullptr, nullptr, nullptr, nullptr, stat_ptr, os, ob);
}